// round 15
// baseline (speedup 1.0000x reference)
#include <cuda_runtime.h>
#include <cuda_bf16.h>
#include <cstdint>

#define EPS    1e-5f
#define CIN    1024
#define PLANES 256
#define HW     4096
#define BATCH  4

// ---------------- scratch (device globals; no allocation) ----------------
__device__ float g_out1[BATCH * PLANES * HW];          // conv1 output fp32 [b][c][p]
__device__ __nv_bfloat16 g_out2h[BATCH * PLANES * HW]; // deform output bf16 hi
__device__ __nv_bfloat16 g_out2l[BATCH * PLANES * HW]; // deform output bf16 lo
__device__ float g_off [BATCH * 18 * HW];
__device__ float g_wofft[2304 * 18];                   // [(c*9+t)][oc]
__device__ __nv_bfloat16 g_w1h[PLANES * CIN];
__device__ __nv_bfloat16 g_w1l[PLANES * CIN];
__device__ __nv_bfloat16 g_w2h[PLANES * 2304];         // tap-major: [o][t*256+c]
__device__ __nv_bfloat16 g_w2l[PLANES * 2304];
__device__ __nv_bfloat16 g_w3h[CIN * PLANES];
__device__ __nv_bfloat16 g_w3l[CIN * PLANES];

// ---------------- f32x2 packed-FMA helpers (off2) ----------------
__device__ __forceinline__ unsigned long long pk2(float lo, float hi) {
    unsigned long long r;
    asm("mov.b64 %0, {%1, %2};" : "=l"(r) : "f"(lo), "f"(hi));
    return r;
}
__device__ __forceinline__ unsigned long long dup2(float v) { return pk2(v, v); }
__device__ __forceinline__ void fma2(unsigned long long& d, unsigned long long a,
                                     unsigned long long b) {
    asm("fma.rn.f32x2 %0, %1, %2, %0;" : "+l"(d) : "l"(a), "l"(b));
}
__device__ __forceinline__ void unpk2(unsigned long long v, float& lo, float& hi) {
    asm("mov.b64 {%0, %1}, %2;" : "=f"(lo), "=f"(hi) : "l"(v));
}

// ---------------- cp.async helpers ----------------
__device__ __forceinline__ void cp16(void* dst, const void* src) {
    unsigned d = (unsigned)__cvta_generic_to_shared(dst);
    asm volatile("cp.async.ca.shared.global [%0], [%1], 16;" :: "r"(d), "l"(src));
}
__device__ __forceinline__ void cp_commit() { asm volatile("cp.async.commit_group;" ::: "memory"); }
__device__ __forceinline__ void cp_wait0()  { asm volatile("cp.async.wait_group 0;" ::: "memory"); }

// ---------------- mma.sync helpers ----------------
__device__ __forceinline__ void ldmA(uint32_t* r, uint32_t addr) {
    asm volatile("ldmatrix.sync.aligned.m8n8.x4.shared.b16 {%0,%1,%2,%3}, [%4];"
        : "=r"(r[0]), "=r"(r[1]), "=r"(r[2]), "=r"(r[3]) : "r"(addr));
}
__device__ __forceinline__ void ldmB4(uint32_t* r, uint32_t addr) {
    asm volatile("ldmatrix.sync.aligned.m8n8.x4.trans.shared.b16 {%0,%1,%2,%3}, [%4];"
        : "=r"(r[0]), "=r"(r[1]), "=r"(r[2]), "=r"(r[3]) : "r"(addr));
}
__device__ __forceinline__ void mma16816(float* c, const uint32_t* a, const uint32_t* b) {
    asm volatile("mma.sync.aligned.m16n8k16.row.col.f32.bf16.bf16.f32 "
        "{%0,%1,%2,%3}, {%4,%5,%6,%7}, {%8,%9}, {%0,%1,%2,%3};"
        : "+f"(c[0]), "+f"(c[1]), "+f"(c[2]), "+f"(c[3])
        : "r"(a[0]), "r"(a[1]), "r"(a[2]), "r"(a[3]), "r"(b[0]), "r"(b[1]));
}
__device__ __forceinline__ void split_bf16(float v, __nv_bfloat16& h, __nv_bfloat16& l) {
    h = __float2bfloat16(v);
    l = __float2bfloat16(v - __bfloat162float(h));
}

// smem layout for conv1/conv3 mma kernels (BK=16)
#define MM_AH 0
#define MM_AL 12288
#define MM_BH 24576
#define MM_BL 41472
#define MM_S  58368
#define MM_T  58880
#define MM_SMEM 59392

// smem layout for deform mma kernel (BK=16, N=64)
#define DF_AH   0                      // [2][256][24] bf16 = 24576
#define DF_AL   24576
#define DF_BH   49152                  // [2][16][72] bf16 = 4608
#define DF_BL   53760
#define DF_MIDX 58368                  // ushort4[576] = 4608
#define DF_MW   62976                  // float4[576]  = 9216
#define DF_S    72192                  // float[256]
#define DF_T    73216                  // float[256]
#define DF_SMEM 74240

// ---------------- merged prep kernel ----------------
// grid ranges: [0,1024) w1-split | [1024,3328) w2-split (tap-major dst) |
//              [3328,4352) w3-split | [4352,4514) wofft | [4514,5666) offinit
__global__ void k_prep(const float* __restrict__ w1, const float* __restrict__ w2,
                       const float* __restrict__ w3, const float* __restrict__ woff,
                       const float* __restrict__ boff) {
    const int bid = blockIdx.x, tid = threadIdx.x;
    if (bid < 1024) {
        int i = bid * 256 + tid;
        float v = w1[i];
        __nv_bfloat16 hh = __float2bfloat16(v);
        g_w1h[i] = hh;
        g_w1l[i] = __float2bfloat16(v - __bfloat162float(hh));
    } else if (bid < 3328) {
        int i = (bid - 1024) * 256 + tid;        // dst index: o*2304 + t*256 + c
        int o = i / 2304, kk = i - o * 2304;
        int t = kk >> 8, c = kk & 255;
        float v = w2[(size_t)o * 2304 + c * 9 + t];
        __nv_bfloat16 hh = __float2bfloat16(v);
        g_w2h[i] = hh;
        g_w2l[i] = __float2bfloat16(v - __bfloat162float(hh));
    } else if (bid < 4352) {
        int i = (bid - 3328) * 256 + tid;
        float v = w3[i];
        __nv_bfloat16 hh = __float2bfloat16(v);
        g_w3h[i] = hh;
        g_w3l[i] = __float2bfloat16(v - __bfloat162float(hh));
    } else if (bid < 4514) {
        int i = (bid - 4352) * 256 + tid;
        if (i < 2304 * 18) {
            int ck = i / 18, oc = i - ck * 18;
            g_wofft[i] = woff[(size_t)oc * 2304 + ck];
        }
    } else {
        int i = (bid - 4514) * 256 + tid;
        if (i < BATCH * 18 * HW) {
            int oc = (i >> 12) % 18;
            g_off[i] = boff[oc];
        }
    }
}

// ================ conv1 (1x1)+BN1+ReLU via mma.sync bf16x3 (BK=16) ================
__global__ __launch_bounds__(512, 1) void k_conv1_mma(
    const float* __restrict__ X,
    const float* __restrict__ ga, const float* __restrict__ be,
    const float* __restrict__ mu, const float* __restrict__ va)
{
    extern __shared__ __align__(16) char sm[];
    const int tid = threadIdx.x;
    const int lane = tid & 31, wid = tid >> 5;
    const int mbase = (wid >> 3) * 64, nbase = (wid & 7) * 32;
    const int b = blockIdx.z, m0 = blockIdx.y * 128, n0 = blockIdx.x * 256;
    const float* Xb = X + (size_t)b * CIN * HW + n0;
    float* O = g_out1 + (size_t)b * PLANES * HW + n0;
    const uint32_t base = (uint32_t)__cvta_generic_to_shared(sm);

    if (tid < 128) {
        int o = m0 + tid;
        float s = ga[o] * rsqrtf(va[o] + EPS);
        ((float*)(sm + MM_S))[tid] = s;
        ((float*)(sm + MM_T))[tid] = be[o] - mu[o] * s;
    }

    float acc[4][4][4];
#pragma unroll
    for (int i = 0; i < 4; ++i)
#pragma unroll
        for (int j = 0; j < 4; ++j)
#pragma unroll
            for (int q = 0; q < 4; ++q) acc[i][j][q] = 0.f;

    const int half = tid & 1;
    const int arow = (tid >> 1) & 127;
    const int asel = tid >> 8;
    const __nv_bfloat16* aw = asel ? g_w1l : g_w1h;
    const int adst = (asel ? MM_AL : MM_AH);

    float4 pv0, pv1;
    const int i0k = tid >> 6,        i0c = (tid & 63) * 4;
    const int i1k = (tid + 512) >> 6, i1c = ((tid + 512) & 63) * 4;

#define C1_CPA(kc, buf)                                                          \
    do {                                                                         \
        cp16(sm + adst + (((buf) * 128 + arow) * 24 + half * 8) * 2,             \
             aw + (size_t)(m0 + arow) * CIN + (kc) * 16 + half * 8);             \
        cp_commit();                                                             \
    } while (0)
#define C1_LDB(kc)                                                               \
    do {                                                                         \
        pv0 = *(const float4*)&Xb[(size_t)((kc) * 16 + i0k) * HW + i0c];         \
        pv1 = *(const float4*)&Xb[(size_t)((kc) * 16 + i1k) * HW + i1c];         \
    } while (0)
#define C1_STB1(v, k, c4, buf)                                                   \
    do {                                                                         \
        __nv_bfloat16 h0, l0, h1, l1, h2, l2, h3, l3;                            \
        split_bf16((v).x, h0, l0); split_bf16((v).y, h1, l1);                    \
        split_bf16((v).z, h2, l2); split_bf16((v).w, h3, l3);                    \
        __nv_bfloat162 hA(h0, h1), hB(h2, h3), lA(l0, l1), lB(l2, l3);           \
        int off = (((buf) * 16 + (k)) * 264 + (c4)) * 2;                         \
        *(uint2*)(sm + MM_BH + off) = make_uint2(*(uint32_t*)&hA, *(uint32_t*)&hB); \
        *(uint2*)(sm + MM_BL + off) = make_uint2(*(uint32_t*)&lA, *(uint32_t*)&lB); \
    } while (0)

    C1_LDB(0);
    C1_CPA(0, 0);
    C1_STB1(pv0, i0k, i0c, 0);
    C1_STB1(pv1, i1k, i1c, 0);
    cp_wait0();
    __syncthreads();

    const int NC = CIN / 16;
    for (int kc = 0; kc < NC; ++kc) {
        const int buf = kc & 1;
        if (kc + 1 < NC) { C1_LDB(kc + 1); C1_CPA(kc + 1, buf ^ 1); }
        {
            uint32_t ah[4][4], al[4][4];
#pragma unroll
            for (int mf = 0; mf < 4; ++mf) {
                uint32_t ro = ((buf * 128 + mbase + mf * 16 + (lane & 15)) * 24
                               + (lane >> 4) * 8) * 2;
                ldmA(ah[mf], base + MM_AH + ro);
                ldmA(al[mf], base + MM_AL + ro);
            }
#pragma unroll
            for (int np = 0; np < 2; ++np) {
                uint32_t ro = ((buf * 16 + (lane & 15)) * 264
                               + nbase + np * 16 + (lane >> 4) * 8) * 2;
                uint32_t bh[4], bl[4];
                ldmB4(bh, base + MM_BH + ro);
                ldmB4(bl, base + MM_BL + ro);
#pragma unroll
                for (int mf = 0; mf < 4; ++mf) {
                    mma16816(acc[mf][2 * np],     ah[mf], bh);
                    mma16816(acc[mf][2 * np],     ah[mf], bl);
                    mma16816(acc[mf][2 * np],     al[mf], bh);
                    mma16816(acc[mf][2 * np + 1], ah[mf], bh + 2);
                    mma16816(acc[mf][2 * np + 1], ah[mf], bl + 2);
                    mma16816(acc[mf][2 * np + 1], al[mf], bh + 2);
                }
            }
        }
        if (kc + 1 < NC) { C1_STB1(pv0, i0k, i0c, buf ^ 1); C1_STB1(pv1, i1k, i1c, buf ^ 1); }
        cp_wait0();
        __syncthreads();
    }

    const int quad = lane >> 2, tq = lane & 3;
    const float* sS = (const float*)(sm + MM_S);
    const float* sT = (const float*)(sm + MM_T);
#pragma unroll
    for (int mf = 0; mf < 4; ++mf) {
        int r0 = mbase + mf * 16 + quad;
        float s0 = sS[r0], t0 = sT[r0], s1 = sS[r0 + 8], t1 = sT[r0 + 8];
#pragma unroll
        for (int nf = 0; nf < 4; ++nf) {
            int c = nbase + nf * 8 + tq * 2;
            float2 v0, v1;
            v0.x = fmaxf(acc[mf][nf][0] * s0 + t0, 0.f);
            v0.y = fmaxf(acc[mf][nf][1] * s0 + t0, 0.f);
            v1.x = fmaxf(acc[mf][nf][2] * s1 + t1, 0.f);
            v1.y = fmaxf(acc[mf][nf][3] * s1 + t1, 0.f);
            *(float2*)&O[(size_t)(m0 + r0) * HW + c]     = v0;
            *(float2*)&O[(size_t)(m0 + r0 + 8) * HW + c] = v1;
        }
    }
}

// ================ conv3 (1x1)+BN3+residual+ReLU via mma.sync bf16x3 (BK=16) =========
__global__ __launch_bounds__(512, 1) void k_conv3_mma(
    const float* __restrict__ X,
    const float* __restrict__ ga, const float* __restrict__ be,
    const float* __restrict__ mu, const float* __restrict__ va,
    float* __restrict__ OUT)
{
    extern __shared__ __align__(16) char sm[];
    const int tid = threadIdx.x;
    const int lane = tid & 31, wid = tid >> 5;
    const int mbase = (wid >> 3) * 64, nbase = (wid & 7) * 32;
    const int b = blockIdx.z, m0 = blockIdx.y * 128, n0 = blockIdx.x * 256;
    const uint32_t base = (uint32_t)__cvta_generic_to_shared(sm);

    if (tid < 128) {
        int o = m0 + tid;
        float s = ga[o] * rsqrtf(va[o] + EPS);
        ((float*)(sm + MM_S))[tid] = s;
        ((float*)(sm + MM_T))[tid] = be[o] - mu[o] * s;
    }

    float acc[4][4][4];
#pragma unroll
    for (int i = 0; i < 4; ++i)
#pragma unroll
        for (int j = 0; j < 4; ++j)
#pragma unroll
            for (int q = 0; q < 4; ++q) acc[i][j][q] = 0.f;

    const int half = tid & 1;
    const int arow = (tid >> 1) & 127;
    const int asel = tid >> 8;
    const __nv_bfloat16* aw = asel ? g_w3l : g_w3h;
    const int adst = (asel ? MM_AL : MM_AH);
    const int j0 = tid, j1 = tid + 512;
    const int b0sel = j0 >> 9, b0k = (j0 & 511) >> 5, b0q = (j0 & 31) * 8;
    const int b1sel = j1 >> 9, b1k = (j1 & 511) >> 5, b1q = (j1 & 31) * 8;
    const __nv_bfloat16* bsrc0 = (b0sel ? g_out2l : g_out2h) + (size_t)b * PLANES * HW + n0;
    const __nv_bfloat16* bsrc1 = (b1sel ? g_out2l : g_out2h) + (size_t)b * PLANES * HW + n0;
    const int bdst0 = b0sel ? MM_BL : MM_BH;
    const int bdst1 = b1sel ? MM_BL : MM_BH;

#define C3_CP(kc, buf)                                                            \
    do {                                                                          \
        cp16(sm + adst + (((buf) * 128 + arow) * 24 + half * 8) * 2,              \
             aw + (size_t)(m0 + arow) * PLANES + (kc) * 16 + half * 8);           \
        cp16(sm + bdst0 + (((buf) * 16 + b0k) * 264 + b0q) * 2,                   \
             bsrc0 + (size_t)((kc) * 16 + b0k) * HW + b0q);                       \
        cp16(sm + bdst1 + (((buf) * 16 + b1k) * 264 + b1q) * 2,                   \
             bsrc1 + (size_t)((kc) * 16 + b1k) * HW + b1q);                       \
        cp_commit();                                                              \
    } while (0)

    C3_CP(0, 0);
    cp_wait0();
    __syncthreads();

    const int NC = PLANES / 16;
    for (int kc = 0; kc < NC; ++kc) {
        const int buf = kc & 1;
        if (kc + 1 < NC) C3_CP(kc + 1, buf ^ 1);
        {
            uint32_t ah[4][4], al[4][4];
#pragma unroll
            for (int mf = 0; mf < 4; ++mf) {
                uint32_t ro = ((buf * 128 + mbase + mf * 16 + (lane & 15)) * 24
                               + (lane >> 4) * 8) * 2;
                ldmA(ah[mf], base + MM_AH + ro);
                ldmA(al[mf], base + MM_AL + ro);
            }
#pragma unroll
            for (int np = 0; np < 2; ++np) {
                uint32_t ro = ((buf * 16 + (lane & 15)) * 264
                               + nbase + np * 16 + (lane >> 4) * 8) * 2;
                uint32_t bh[4], bl[4];
                ldmB4(bh, base + MM_BH + ro);
                ldmB4(bl, base + MM_BL + ro);
#pragma unroll
                for (int mf = 0; mf < 4; ++mf) {
                    mma16816(acc[mf][2 * np],     ah[mf], bh);
                    mma16816(acc[mf][2 * np],     ah[mf], bl);
                    mma16816(acc[mf][2 * np],     al[mf], bh);
                    mma16816(acc[mf][2 * np + 1], ah[mf], bh + 2);
                    mma16816(acc[mf][2 * np + 1], ah[mf], bl + 2);
                    mma16816(acc[mf][2 * np + 1], al[mf], bh + 2);
                }
            }
        }
        cp_wait0();
        __syncthreads();
    }

    const int quad = lane >> 2, tq = lane & 3;
    const float* sS = (const float*)(sm + MM_S);
    const float* sT = (const float*)(sm + MM_T);
#pragma unroll
    for (int mf = 0; mf < 4; ++mf) {
        int r0 = mbase + mf * 16 + quad;
        float s0 = sS[r0], t0 = sT[r0], s1 = sS[r0 + 8], t1 = sT[r0 + 8];
#pragma unroll
        for (int nf = 0; nf < 4; ++nf) {
            int c = nbase + nf * 8 + tq * 2;
            size_t gi0 = ((size_t)b * CIN + m0 + r0) * HW + n0 + c;
            size_t gi1 = gi0 + (size_t)8 * HW;
            float2 x0 = *(const float2*)&X[gi0];
            float2 x1 = *(const float2*)&X[gi1];
            float2 v0, v1;
            v0.x = fmaxf(acc[mf][nf][0] * s0 + t0 + x0.x, 0.f);
            v0.y = fmaxf(acc[mf][nf][1] * s0 + t0 + x0.y, 0.f);
            v1.x = fmaxf(acc[mf][nf][2] * s1 + t1 + x1.x, 0.f);
            v1.y = fmaxf(acc[mf][nf][3] * s1 + t1 + x1.y, 0.f);
            *(float2*)&OUT[gi0] = v0;
            *(float2*)&OUT[gi1] = v1;
        }
    }
}

// ================ offset conv (3x3 dil=2, 18 oc) — f32x2 over oc pairs ===========
__global__ __launch_bounds__(256, 2) void k_off2()
{
    const int rg    = blockIdx.x;
    const int b     = blockIdx.y;
    const int chunk = blockIdx.z;
    const int tid = threadIdx.x;
    const int r   = tid >> 4;
    const int x0  = (tid & 15) * 4;
    const int y0  = rg * 16;
    const int cbase = chunk * 32;

    __shared__ __align__(16) float halo[2][20 * 72];
    __shared__ __align__(16) float wt[32 * 9 * 18];

    for (int i = tid; i < 288 * 18; i += 256)
        wt[i] = g_wofft[(size_t)cbase * 9 * 18 + i];

    const float* plbase = g_out1 + ((size_t)b * PLANES + cbase) * HW;

    unsigned long long acc2[9][4];
#pragma unroll
    for (int op = 0; op < 9; ++op)
#pragma unroll
        for (int j = 0; j < 4; ++j) acc2[op][j] = 0ull;

    for (int i = tid; i < 1440; i += 256) {
        int ry = i / 72, rx = i % 72;
        int gy = y0 - 2 + ry, gx = rx - 2;
        halo[0][i] = ((unsigned)gy < 64u && (unsigned)gx < 64u)
                     ? plbase[gy * 64 + gx] : 0.f;
    }
    __syncthreads();

    for (int cl = 0; cl < 32; ++cl) {
        int buf = cl & 1;
        float fv[6];
        if (cl < 31) {
            const float* pl = plbase + (size_t)(cl + 1) * HW;
#pragma unroll
            for (int i = 0; i < 6; ++i) {
                int idx = tid + i * 256;
                float v = 0.f;
                if (idx < 1440) {
                    int ry = idx / 72, rx = idx % 72;
                    int gy = y0 - 2 + ry, gx = rx - 2;
                    if ((unsigned)gy < 64u && (unsigned)gx < 64u) v = pl[gy * 64 + gx];
                }
                fv[i] = v;
            }
        }
        const float* hb = &halo[buf][0];
#pragma unroll
        for (int t = 0; t < 9; ++t) {
            int dy = (t / 3) * 2, dx = (t % 3) * 2;
            const float* hp = hb + (r + dy) * 72 + x0 + dx;
            float2 sA = *(const float2*)hp;
            float2 sB = *(const float2*)(hp + 2);
            unsigned long long d0 = dup2(sA.x), d1 = dup2(sA.y);
            unsigned long long d2 = dup2(sB.x), d3 = dup2(sB.y);
            const float* wrow = &wt[(cl * 9 + t) * 18];
#pragma unroll
            for (int op = 0; op < 9; ++op) {
                float2 wp = *(const float2*)&wrow[op * 2];
                unsigned long long wv = pk2(wp.x, wp.y);
                fma2(acc2[op][0], wv, d0);
                fma2(acc2[op][1], wv, d1);
                fma2(acc2[op][2], wv, d2);
                fma2(acc2[op][3], wv, d3);
            }
        }
        if (cl < 31) {
#pragma unroll
            for (int i = 0; i < 6; ++i) {
                int idx = tid + i * 256;
                if (idx < 1440) halo[buf ^ 1][idx] = fv[i];
            }
        }
        __syncthreads();
    }

    const int px = (y0 + r) * 64 + x0;
    float* ob = g_off + (size_t)b * 18 * HW + px;
#pragma unroll
    for (int op = 0; op < 9; ++op)
#pragma unroll
        for (int j = 0; j < 4; ++j) {
            float lo, hi;
            unpk2(acc2[op][j], lo, hi);
            atomicAdd(ob + (size_t)(2 * op)     * HW + j, lo);
            atomicAdd(ob + (size_t)(2 * op + 1) * HW + j, hi);
        }
}

// ================ deform conv via mma.sync bf16x3 (BK=16, N=64, 2 CTAs/SM) ========
// CTA: M=256 outputs x N=64 px, K=2304 tap-major in 144 chunks of 16.
// 256 thr = 8 warps as 4M x 2N (warp 64x32).
__global__ __launch_bounds__(256, 2) void k_deform_mma(
    const float* __restrict__ bc2,
    const float* __restrict__ ga, const float* __restrict__ be,
    const float* __restrict__ mu, const float* __restrict__ va)
{
    extern __shared__ __align__(16) char sm[];
    const int tid = threadIdx.x;
    const int lane = tid & 31, wid = tid >> 5;
    const int mbase = (wid >> 1) * 64, nbase = (wid & 1) * 32;
    const int b = blockIdx.y, n0 = blockIdx.x * 64;
    const float* out1b = g_out1 + (size_t)b * PLANES * HW;
    const float* offb  = g_off  + (size_t)b * 18 * HW;
    __nv_bfloat16* Oh = g_out2h + (size_t)b * PLANES * HW;
    __nv_bfloat16* Ol = g_out2l + (size_t)b * PLANES * HW;
    const uint32_t base = (uint32_t)__cvta_generic_to_shared(sm);

    {
        float s = ga[tid] * rsqrtf(va[tid] + EPS);
        float t = be[tid] - mu[tid] * s + bc2[tid] * s;
        ((float*)(sm + DF_S))[tid] = s;
        ((float*)(sm + DF_T))[tid] = t;
    }

    // per-(tap,pixel) bilinear metadata: 9 taps x 64 px
    ushort4* MIDX = (ushort4*)(sm + DF_MIDX);
    float4*  MW   = (float4*) (sm + DF_MW);
    for (int idx = tid; idx < 9 * 64; idx += 256) {
        int k = idx >> 6, j = idx & 63;
        int p = n0 + j;
        int h = p >> 6, w = p & 63;
        float oy = offb[(size_t)(2 * k)     * HW + p];
        float ox = offb[(size_t)(2 * k + 1) * HW + p];
        float py = (float)(h + (k / 3) * 2 - 2) + oy;
        float px = (float)(w + (k % 3) * 2 - 2) + ox;
        float fy = floorf(py), fx = floorf(px);
        int y0 = (int)fy, x0 = (int)fx;
        float wy = py - fy, wx = px - fx;
        bool y0v = (unsigned)y0 < 64u, y1v = (unsigned)(y0 + 1) < 64u;
        bool x0v = (unsigned)x0 < 64u, x1v = (unsigned)(x0 + 1) < 64u;
        float w00 = (1.f - wy) * (1.f - wx) * (float)(y0v && x0v);
        float w01 = (1.f - wy) * wx         * (float)(y0v && x1v);
        float w10 = wy * (1.f - wx)         * (float)(y1v && x0v);
        float w11 = wy * wx                 * (float)(y1v && x1v);
        int y0c = min(max(y0, 0), 63),  y1c = min(max(y0 + 1, 0), 63);
        int x0c = min(max(x0, 0), 63),  x1c = min(max(x0 + 1, 0), 63);
        MIDX[idx] = make_ushort4((unsigned short)(y0c * 64 + x0c),
                                 (unsigned short)(y0c * 64 + x1c),
                                 (unsigned short)(y1c * 64 + x0c),
                                 (unsigned short)(y1c * 64 + x1c));
        MW[idx]   = make_float4(w00, w01, w10, w11);
    }
    __syncthreads();

    float acc[4][4][4];
#pragma unroll
    for (int i = 0; i < 4; ++i)
#pragma unroll
        for (int j = 0; j < 4; ++j)
#pragma unroll
            for (int q = 0; q < 4; ++q) acc[i][j][q] = 0.f;

    auto issueA = [&](int kc, int buf) {
#pragma unroll
        for (int t2 = 0; t2 < 2; ++t2) {
            int i = tid + t2 * 256;
            int r = i >> 1, part = (i & 1) * 8;
            cp16(sm + DF_AH + (((buf) * 256 + r) * 24 + part) * 2,
                 g_w2h + (size_t)r * 2304 + kc * 16 + part);
            cp16(sm + DF_AL + (((buf) * 256 + r) * 24 + part) * 2,
                 g_w2l + (size_t)r * 2304 + kc * 16 + part);
        }
        cp_commit();
    };

    const int gkk = tid >> 4;           // 0..15
    const int gpx = (tid & 15) * 4;     // 0..60
    auto buildB = [&](int kc, int buf) {
        // tap-major K: tap constant per chunk
        int t = kc >> 4;
        int c = ((kc & 15) << 4) + gkk;
        const float* pl = out1b + (size_t)c * HW;
        const int mb = t * 64 + gpx;
        uint32_t hp[2], lp[2];
#pragma unroll
        for (int jj = 0; jj < 2; ++jj) {
            __nv_bfloat16 h0, l0, h1, l1;
            {
                ushort4 id = MIDX[mb + jj * 2];
                float4  w  = MW[mb + jj * 2];
                float v = pl[id.x] * w.x;
                v = fmaf(pl[id.y], w.y, v);
                v = fmaf(pl[id.z], w.z, v);
                v = fmaf(pl[id.w], w.w, v);
                split_bf16(v, h0, l0);
            }
            {
                ushort4 id = MIDX[mb + jj * 2 + 1];
                float4  w  = MW[mb + jj * 2 + 1];
                float v = pl[id.x] * w.x;
                v = fmaf(pl[id.y], w.y, v);
                v = fmaf(pl[id.z], w.z, v);
                v = fmaf(pl[id.w], w.w, v);
                split_bf16(v, h1, l1);
            }
            __nv_bfloat162 hh(h0, h1), ll(l0, l1);
            hp[jj] = *(uint32_t*)&hh;
            lp[jj] = *(uint32_t*)&ll;
        }
        int off = ((buf * 16 + gkk) * 72 + gpx) * 2;
        *(uint2*)(sm + DF_BH + off) = make_uint2(hp[0], hp[1]);
        *(uint2*)(sm + DF_BL + off) = make_uint2(lp[0], lp[1]);
    };

    issueA(0, 0);
    buildB(0, 0);
    cp_wait0();
    __syncthreads();

    const int NC = 144;
    for (int kc = 0; kc < NC; ++kc) {
        const int buf = kc & 1;
        if (kc + 1 < NC) issueA(kc + 1, buf ^ 1);
        {
            uint32_t ah[4][4], al[4][4];
#pragma unroll
            for (int mf = 0; mf < 4; ++mf) {
                uint32_t ro = ((buf * 256 + mbase + mf * 16 + (lane & 15)) * 24
                               + (lane >> 4) * 8) * 2;
                ldmA(ah[mf], base + DF_AH + ro);
                ldmA(al[mf], base + DF_AL + ro);
            }
#pragma unroll
            for (int np = 0; np < 2; ++np) {
                uint32_t ro = ((buf * 16 + (lane & 15)) * 72
                               + nbase + np * 16 + (lane >> 4) * 8) * 2;
                uint32_t bh[4], bl[4];
                ldmB4(bh, base + DF_BH + ro);
                ldmB4(bl, base + DF_BL + ro);
#pragma unroll
                for (int mf = 0; mf < 4; ++mf) {
                    mma16816(acc[mf][2 * np],     ah[mf], bh);
                    mma16816(acc[mf][2 * np],     ah[mf], bl);
                    mma16816(acc[mf][2 * np],     al[mf], bh);
                    mma16816(acc[mf][2 * np + 1], ah[mf], bh + 2);
                    mma16816(acc[mf][2 * np + 1], ah[mf], bl + 2);
                    mma16816(acc[mf][2 * np + 1], al[mf], bh + 2);
                }
            }
        }
        if (kc + 1 < NC) buildB(kc + 1, buf ^ 1);
        cp_wait0();
        __syncthreads();
    }

    const int quad = lane >> 2, tq = lane & 3;
    const float* sS = (const float*)(sm + DF_S);
    const float* sT = (const float*)(sm + DF_T);
#pragma unroll
    for (int mf = 0; mf < 4; ++mf) {
        int r0 = mbase + mf * 16 + quad;
        float s0 = sS[r0], t0 = sT[r0], s1 = sS[r0 + 8], t1 = sT[r0 + 8];
#pragma unroll
        for (int nf = 0; nf < 4; ++nf) {
            int c = nbase + nf * 8 + tq * 2;
            float y00 = fmaxf(acc[mf][nf][0] * s0 + t0, 0.f);
            float y01 = fmaxf(acc[mf][nf][1] * s0 + t0, 0.f);
            float y10 = fmaxf(acc[mf][nf][2] * s1 + t1, 0.f);
            float y11 = fmaxf(acc[mf][nf][3] * s1 + t1, 0.f);
            __nv_bfloat16 h0, l0, h1, l1, h2, l2, h3, l3;
            split_bf16(y00, h0, l0); split_bf16(y01, h1, l1);
            split_bf16(y10, h2, l2); split_bf16(y11, h3, l3);
            __nv_bfloat162 hA(h0, h1), lA(l0, l1), hB(h2, h3), lB(l2, l3);
            size_t gi0 = (size_t)r0 * HW + n0 + c;
            size_t gi1 = gi0 + (size_t)8 * HW;
            *(uint32_t*)&Oh[gi0] = *(uint32_t*)&hA;
            *(uint32_t*)&Ol[gi0] = *(uint32_t*)&lA;
            *(uint32_t*)&Oh[gi1] = *(uint32_t*)&hB;
            *(uint32_t*)&Ol[gi1] = *(uint32_t*)&lB;
        }
    }
}

// ---------------- launch ----------------
extern "C" void kernel_launch(void* const* d_in, const int* in_sizes, int n_in,
                              void* d_out, int out_size) {
    const float* x      = (const float*)d_in[0];
    const float* w1     = (const float*)d_in[1];
    const float* gamma1 = (const float*)d_in[2];
    const float* beta1  = (const float*)d_in[3];
    const float* mean1  = (const float*)d_in[4];
    const float* var1   = (const float*)d_in[5];
    const float* woff   = (const float*)d_in[6];
    const float* boff   = (const float*)d_in[7];
    const float* w2     = (const float*)d_in[8];
    const float* bconv2 = (const float*)d_in[9];
    const float* gamma2 = (const float*)d_in[10];
    const float* beta2  = (const float*)d_in[11];
    const float* mean2  = (const float*)d_in[12];
    const float* var2   = (const float*)d_in[13];
    const float* w3     = (const float*)d_in[14];
    const float* gamma3 = (const float*)d_in[15];
    const float* beta3  = (const float*)d_in[16];
    const float* mean3  = (const float*)d_in[17];
    const float* var3   = (const float*)d_in[18];

    cudaFuncSetAttribute(k_conv1_mma, cudaFuncAttributeMaxDynamicSharedMemorySize, MM_SMEM);
    cudaFuncSetAttribute(k_conv3_mma, cudaFuncAttributeMaxDynamicSharedMemorySize, MM_SMEM);
    cudaFuncSetAttribute(k_deform_mma, cudaFuncAttributeMaxDynamicSharedMemorySize, DF_SMEM);

    k_prep<<<5666, 256>>>(w1, w2, w3, woff, boff);
    k_conv1_mma<<<dim3(16, 2, BATCH), 512, MM_SMEM>>>(x, gamma1, beta1, mean1, var1);
    k_off2<<<dim3(4, BATCH, 8), 256>>>();
    k_deform_mma<<<dim3(64, BATCH), 256, DF_SMEM>>>(bconv2, gamma2, beta2, mean2, var2);
    k_conv3_mma<<<dim3(16, 8, BATCH), 512, MM_SMEM>>>(x, gamma3, beta3, mean3, var3,
                                                      (float*)d_out);
}

// round 16
// speedup vs baseline: 1.2509x; 1.2509x over previous
#include <cuda_runtime.h>
#include <cuda_bf16.h>
#include <cstdint>

#define EPS    1e-5f
#define CIN    1024
#define PLANES 256
#define HW     4096
#define BATCH  4

// ---------------- scratch (device globals; no allocation) ----------------
__device__ float g_out1[BATCH * PLANES * HW];          // conv1 output fp32 [b][c][p]
__device__ __nv_bfloat16 g_out2h[BATCH * PLANES * HW]; // deform output bf16 hi
__device__ __nv_bfloat16 g_out2l[BATCH * PLANES * HW]; // deform output bf16 lo
__device__ float g_off [BATCH * 18 * HW];
__device__ float g_wofft[2304 * 18];                   // [(c*9+t)][oc]
__device__ __nv_bfloat16 g_w1h[PLANES * CIN];
__device__ __nv_bfloat16 g_w1l[PLANES * CIN];
__device__ __nv_bfloat16 g_w2h[PLANES * 2304];         // tap-major: [o][t*256+c]
__device__ __nv_bfloat16 g_w2l[PLANES * 2304];
__device__ __nv_bfloat16 g_w3h[CIN * PLANES];
__device__ __nv_bfloat16 g_w3l[CIN * PLANES];

// ---------------- f32x2 packed-FMA helpers (off2) ----------------
__device__ __forceinline__ unsigned long long pk2(float lo, float hi) {
    unsigned long long r;
    asm("mov.b64 %0, {%1, %2};" : "=l"(r) : "f"(lo), "f"(hi));
    return r;
}
__device__ __forceinline__ unsigned long long dup2(float v) { return pk2(v, v); }
__device__ __forceinline__ void fma2(unsigned long long& d, unsigned long long a,
                                     unsigned long long b) {
    asm("fma.rn.f32x2 %0, %1, %2, %0;" : "+l"(d) : "l"(a), "l"(b));
}
__device__ __forceinline__ void unpk2(unsigned long long v, float& lo, float& hi) {
    asm("mov.b64 {%0, %1}, %2;" : "=f"(lo), "=f"(hi) : "l"(v));
}

// ---------------- cp.async helpers ----------------
__device__ __forceinline__ void cp16(void* dst, const void* src) {
    unsigned d = (unsigned)__cvta_generic_to_shared(dst);
    asm volatile("cp.async.ca.shared.global [%0], [%1], 16;" :: "r"(d), "l"(src));
}
__device__ __forceinline__ void cp_commit() { asm volatile("cp.async.commit_group;" ::: "memory"); }
__device__ __forceinline__ void cp_wait0()  { asm volatile("cp.async.wait_group 0;" ::: "memory"); }

// ---------------- mma.sync helpers ----------------
__device__ __forceinline__ void ldmA(uint32_t* r, uint32_t addr) {
    asm volatile("ldmatrix.sync.aligned.m8n8.x4.shared.b16 {%0,%1,%2,%3}, [%4];"
        : "=r"(r[0]), "=r"(r[1]), "=r"(r[2]), "=r"(r[3]) : "r"(addr));
}
__device__ __forceinline__ void ldmB4(uint32_t* r, uint32_t addr) {
    asm volatile("ldmatrix.sync.aligned.m8n8.x4.trans.shared.b16 {%0,%1,%2,%3}, [%4];"
        : "=r"(r[0]), "=r"(r[1]), "=r"(r[2]), "=r"(r[3]) : "r"(addr));
}
__device__ __forceinline__ void mma16816(float* c, const uint32_t* a, const uint32_t* b) {
    asm volatile("mma.sync.aligned.m16n8k16.row.col.f32.bf16.bf16.f32 "
        "{%0,%1,%2,%3}, {%4,%5,%6,%7}, {%8,%9}, {%0,%1,%2,%3};"
        : "+f"(c[0]), "+f"(c[1]), "+f"(c[2]), "+f"(c[3])
        : "r"(a[0]), "r"(a[1]), "r"(a[2]), "r"(a[3]), "r"(b[0]), "r"(b[1]));
}
__device__ __forceinline__ void split_bf16(float v, __nv_bfloat16& h, __nv_bfloat16& l) {
    h = __float2bfloat16(v);
    l = __float2bfloat16(v - __bfloat162float(h));
}

// smem layout for conv1/conv3 mma kernels (BK=16)
#define MM_AH 0
#define MM_AL 12288
#define MM_BH 24576
#define MM_BL 41472
#define MM_S  58368
#define MM_T  58880
#define MM_SMEM 59392

// smem layout for deform mma kernel (BK=16, N=128)
#define DF_AH   0                      // [2][256][24] bf16 = 24576
#define DF_AL   24576
#define DF_BH   49152                  // [2][16][136] bf16 = 8704
#define DF_BL   57856
#define DF_MIDX 66560                  // ushort4[1152] = 9216
#define DF_MW   75776                  // float4[1152]  = 18432
#define DF_S    94208                  // float[256]
#define DF_T    95232                  // float[256]
#define DF_SMEM 96256

// ---------------- merged prep kernel ----------------
// grid ranges: [0,1024) w1-split | [1024,3328) w2-split (tap-major dst) |
//              [3328,4352) w3-split | [4352,4514) wofft | [4514,5666) offinit
__global__ void k_prep(const float* __restrict__ w1, const float* __restrict__ w2,
                       const float* __restrict__ w3, const float* __restrict__ woff,
                       const float* __restrict__ boff) {
    const int bid = blockIdx.x, tid = threadIdx.x;
    if (bid < 1024) {
        int i = bid * 256 + tid;
        float v = w1[i];
        __nv_bfloat16 hh = __float2bfloat16(v);
        g_w1h[i] = hh;
        g_w1l[i] = __float2bfloat16(v - __bfloat162float(hh));
    } else if (bid < 3328) {
        int i = (bid - 1024) * 256 + tid;        // dst index: o*2304 + t*256 + c
        int o = i / 2304, kk = i - o * 2304;
        int t = kk >> 8, c = kk & 255;
        float v = w2[(size_t)o * 2304 + c * 9 + t];
        __nv_bfloat16 hh = __float2bfloat16(v);
        g_w2h[i] = hh;
        g_w2l[i] = __float2bfloat16(v - __bfloat162float(hh));
    } else if (bid < 4352) {
        int i = (bid - 3328) * 256 + tid;
        float v = w3[i];
        __nv_bfloat16 hh = __float2bfloat16(v);
        g_w3h[i] = hh;
        g_w3l[i] = __float2bfloat16(v - __bfloat162float(hh));
    } else if (bid < 4514) {
        int i = (bid - 4352) * 256 + tid;
        if (i < 2304 * 18) {
            int ck = i / 18, oc = i - ck * 18;
            g_wofft[i] = woff[(size_t)oc * 2304 + ck];
        }
    } else {
        int i = (bid - 4514) * 256 + tid;
        if (i < BATCH * 18 * HW) {
            int oc = (i >> 12) % 18;
            g_off[i] = boff[oc];
        }
    }
}

// ================ conv1 (1x1)+BN1+ReLU via mma.sync bf16x3 (BK=16) ================
__global__ __launch_bounds__(512, 1) void k_conv1_mma(
    const float* __restrict__ X,
    const float* __restrict__ ga, const float* __restrict__ be,
    const float* __restrict__ mu, const float* __restrict__ va)
{
    extern __shared__ __align__(16) char sm[];
    const int tid = threadIdx.x;
    const int lane = tid & 31, wid = tid >> 5;
    const int mbase = (wid >> 3) * 64, nbase = (wid & 7) * 32;
    const int b = blockIdx.z, m0 = blockIdx.y * 128, n0 = blockIdx.x * 256;
    const float* Xb = X + (size_t)b * CIN * HW + n0;
    float* O = g_out1 + (size_t)b * PLANES * HW + n0;
    const uint32_t base = (uint32_t)__cvta_generic_to_shared(sm);

    if (tid < 128) {
        int o = m0 + tid;
        float s = ga[o] * rsqrtf(va[o] + EPS);
        ((float*)(sm + MM_S))[tid] = s;
        ((float*)(sm + MM_T))[tid] = be[o] - mu[o] * s;
    }

    float acc[4][4][4];
#pragma unroll
    for (int i = 0; i < 4; ++i)
#pragma unroll
        for (int j = 0; j < 4; ++j)
#pragma unroll
            for (int q = 0; q < 4; ++q) acc[i][j][q] = 0.f;

    const int half = tid & 1;
    const int arow = (tid >> 1) & 127;
    const int asel = tid >> 8;
    const __nv_bfloat16* aw = asel ? g_w1l : g_w1h;
    const int adst = (asel ? MM_AL : MM_AH);

    float4 pv0, pv1;
    const int i0k = tid >> 6,        i0c = (tid & 63) * 4;
    const int i1k = (tid + 512) >> 6, i1c = ((tid + 512) & 63) * 4;

#define C1_CPA(kc, buf)                                                          \
    do {                                                                         \
        cp16(sm + adst + (((buf) * 128 + arow) * 24 + half * 8) * 2,             \
             aw + (size_t)(m0 + arow) * CIN + (kc) * 16 + half * 8);             \
        cp_commit();                                                             \
    } while (0)
#define C1_LDB(kc)                                                               \
    do {                                                                         \
        pv0 = *(const float4*)&Xb[(size_t)((kc) * 16 + i0k) * HW + i0c];         \
        pv1 = *(const float4*)&Xb[(size_t)((kc) * 16 + i1k) * HW + i1c];         \
    } while (0)
#define C1_STB1(v, k, c4, buf)                                                   \
    do {                                                                         \
        __nv_bfloat16 h0, l0, h1, l1, h2, l2, h3, l3;                            \
        split_bf16((v).x, h0, l0); split_bf16((v).y, h1, l1);                    \
        split_bf16((v).z, h2, l2); split_bf16((v).w, h3, l3);                    \
        __nv_bfloat162 hA(h0, h1), hB(h2, h3), lA(l0, l1), lB(l2, l3);           \
        int off = (((buf) * 16 + (k)) * 264 + (c4)) * 2;                         \
        *(uint2*)(sm + MM_BH + off) = make_uint2(*(uint32_t*)&hA, *(uint32_t*)&hB); \
        *(uint2*)(sm + MM_BL + off) = make_uint2(*(uint32_t*)&lA, *(uint32_t*)&lB); \
    } while (0)

    C1_LDB(0);
    C1_CPA(0, 0);
    C1_STB1(pv0, i0k, i0c, 0);
    C1_STB1(pv1, i1k, i1c, 0);
    cp_wait0();
    __syncthreads();

    const int NC = CIN / 16;
    for (int kc = 0; kc < NC; ++kc) {
        const int buf = kc & 1;
        if (kc + 1 < NC) { C1_LDB(kc + 1); C1_CPA(kc + 1, buf ^ 1); }
        {
            uint32_t ah[4][4], al[4][4];
#pragma unroll
            for (int mf = 0; mf < 4; ++mf) {
                uint32_t ro = ((buf * 128 + mbase + mf * 16 + (lane & 15)) * 24
                               + (lane >> 4) * 8) * 2;
                ldmA(ah[mf], base + MM_AH + ro);
                ldmA(al[mf], base + MM_AL + ro);
            }
#pragma unroll
            for (int np = 0; np < 2; ++np) {
                uint32_t ro = ((buf * 16 + (lane & 15)) * 264
                               + nbase + np * 16 + (lane >> 4) * 8) * 2;
                uint32_t bh[4], bl[4];
                ldmB4(bh, base + MM_BH + ro);
                ldmB4(bl, base + MM_BL + ro);
#pragma unroll
                for (int mf = 0; mf < 4; ++mf) {
                    mma16816(acc[mf][2 * np],     ah[mf], bh);
                    mma16816(acc[mf][2 * np],     ah[mf], bl);
                    mma16816(acc[mf][2 * np],     al[mf], bh);
                    mma16816(acc[mf][2 * np + 1], ah[mf], bh + 2);
                    mma16816(acc[mf][2 * np + 1], ah[mf], bl + 2);
                    mma16816(acc[mf][2 * np + 1], al[mf], bh + 2);
                }
            }
        }
        if (kc + 1 < NC) { C1_STB1(pv0, i0k, i0c, buf ^ 1); C1_STB1(pv1, i1k, i1c, buf ^ 1); }
        cp_wait0();
        __syncthreads();
    }

    const int quad = lane >> 2, tq = lane & 3;
    const float* sS = (const float*)(sm + MM_S);
    const float* sT = (const float*)(sm + MM_T);
#pragma unroll
    for (int mf = 0; mf < 4; ++mf) {
        int r0 = mbase + mf * 16 + quad;
        float s0 = sS[r0], t0 = sT[r0], s1 = sS[r0 + 8], t1 = sT[r0 + 8];
#pragma unroll
        for (int nf = 0; nf < 4; ++nf) {
            int c = nbase + nf * 8 + tq * 2;
            float2 v0, v1;
            v0.x = fmaxf(acc[mf][nf][0] * s0 + t0, 0.f);
            v0.y = fmaxf(acc[mf][nf][1] * s0 + t0, 0.f);
            v1.x = fmaxf(acc[mf][nf][2] * s1 + t1, 0.f);
            v1.y = fmaxf(acc[mf][nf][3] * s1 + t1, 0.f);
            *(float2*)&O[(size_t)(m0 + r0) * HW + c]     = v0;
            *(float2*)&O[(size_t)(m0 + r0 + 8) * HW + c] = v1;
        }
    }
}

// ================ conv3 (1x1)+BN3+residual+ReLU via mma.sync bf16x3 (BK=16) =========
__global__ __launch_bounds__(512, 1) void k_conv3_mma(
    const float* __restrict__ X,
    const float* __restrict__ ga, const float* __restrict__ be,
    const float* __restrict__ mu, const float* __restrict__ va,
    float* __restrict__ OUT)
{
    extern __shared__ __align__(16) char sm[];
    const int tid = threadIdx.x;
    const int lane = tid & 31, wid = tid >> 5;
    const int mbase = (wid >> 3) * 64, nbase = (wid & 7) * 32;
    const int b = blockIdx.z, m0 = blockIdx.y * 128, n0 = blockIdx.x * 256;
    const uint32_t base = (uint32_t)__cvta_generic_to_shared(sm);

    if (tid < 128) {
        int o = m0 + tid;
        float s = ga[o] * rsqrtf(va[o] + EPS);
        ((float*)(sm + MM_S))[tid] = s;
        ((float*)(sm + MM_T))[tid] = be[o] - mu[o] * s;
    }

    float acc[4][4][4];
#pragma unroll
    for (int i = 0; i < 4; ++i)
#pragma unroll
        for (int j = 0; j < 4; ++j)
#pragma unroll
            for (int q = 0; q < 4; ++q) acc[i][j][q] = 0.f;

    const int half = tid & 1;
    const int arow = (tid >> 1) & 127;
    const int asel = tid >> 8;
    const __nv_bfloat16* aw = asel ? g_w3l : g_w3h;
    const int adst = (asel ? MM_AL : MM_AH);
    const int j0 = tid, j1 = tid + 512;
    const int b0sel = j0 >> 9, b0k = (j0 & 511) >> 5, b0q = (j0 & 31) * 8;
    const int b1sel = j1 >> 9, b1k = (j1 & 511) >> 5, b1q = (j1 & 31) * 8;
    const __nv_bfloat16* bsrc0 = (b0sel ? g_out2l : g_out2h) + (size_t)b * PLANES * HW + n0;
    const __nv_bfloat16* bsrc1 = (b1sel ? g_out2l : g_out2h) + (size_t)b * PLANES * HW + n0;
    const int bdst0 = b0sel ? MM_BL : MM_BH;
    const int bdst1 = b1sel ? MM_BL : MM_BH;

#define C3_CP(kc, buf)                                                            \
    do {                                                                          \
        cp16(sm + adst + (((buf) * 128 + arow) * 24 + half * 8) * 2,              \
             aw + (size_t)(m0 + arow) * PLANES + (kc) * 16 + half * 8);           \
        cp16(sm + bdst0 + (((buf) * 16 + b0k) * 264 + b0q) * 2,                   \
             bsrc0 + (size_t)((kc) * 16 + b0k) * HW + b0q);                       \
        cp16(sm + bdst1 + (((buf) * 16 + b1k) * 264 + b1q) * 2,                   \
             bsrc1 + (size_t)((kc) * 16 + b1k) * HW + b1q);                       \
        cp_commit();                                                              \
    } while (0)

    C3_CP(0, 0);
    cp_wait0();
    __syncthreads();

    const int NC = PLANES / 16;
    for (int kc = 0; kc < NC; ++kc) {
        const int buf = kc & 1;
        if (kc + 1 < NC) C3_CP(kc + 1, buf ^ 1);
        {
            uint32_t ah[4][4], al[4][4];
#pragma unroll
            for (int mf = 0; mf < 4; ++mf) {
                uint32_t ro = ((buf * 128 + mbase + mf * 16 + (lane & 15)) * 24
                               + (lane >> 4) * 8) * 2;
                ldmA(ah[mf], base + MM_AH + ro);
                ldmA(al[mf], base + MM_AL + ro);
            }
#pragma unroll
            for (int np = 0; np < 2; ++np) {
                uint32_t ro = ((buf * 16 + (lane & 15)) * 264
                               + nbase + np * 16 + (lane >> 4) * 8) * 2;
                uint32_t bh[4], bl[4];
                ldmB4(bh, base + MM_BH + ro);
                ldmB4(bl, base + MM_BL + ro);
#pragma unroll
                for (int mf = 0; mf < 4; ++mf) {
                    mma16816(acc[mf][2 * np],     ah[mf], bh);
                    mma16816(acc[mf][2 * np],     ah[mf], bl);
                    mma16816(acc[mf][2 * np],     al[mf], bh);
                    mma16816(acc[mf][2 * np + 1], ah[mf], bh + 2);
                    mma16816(acc[mf][2 * np + 1], ah[mf], bl + 2);
                    mma16816(acc[mf][2 * np + 1], al[mf], bh + 2);
                }
            }
        }
        cp_wait0();
        __syncthreads();
    }

    const int quad = lane >> 2, tq = lane & 3;
    const float* sS = (const float*)(sm + MM_S);
    const float* sT = (const float*)(sm + MM_T);
#pragma unroll
    for (int mf = 0; mf < 4; ++mf) {
        int r0 = mbase + mf * 16 + quad;
        float s0 = sS[r0], t0 = sT[r0], s1 = sS[r0 + 8], t1 = sT[r0 + 8];
#pragma unroll
        for (int nf = 0; nf < 4; ++nf) {
            int c = nbase + nf * 8 + tq * 2;
            size_t gi0 = ((size_t)b * CIN + m0 + r0) * HW + n0 + c;
            size_t gi1 = gi0 + (size_t)8 * HW;
            float2 x0 = *(const float2*)&X[gi0];
            float2 x1 = *(const float2*)&X[gi1];
            float2 v0, v1;
            v0.x = fmaxf(acc[mf][nf][0] * s0 + t0 + x0.x, 0.f);
            v0.y = fmaxf(acc[mf][nf][1] * s0 + t0 + x0.y, 0.f);
            v1.x = fmaxf(acc[mf][nf][2] * s1 + t1 + x1.x, 0.f);
            v1.y = fmaxf(acc[mf][nf][3] * s1 + t1 + x1.y, 0.f);
            *(float2*)&OUT[gi0] = v0;
            *(float2*)&OUT[gi1] = v1;
        }
    }
}

// ================ offset conv (3x3 dil=2, 18 oc) — f32x2 over oc pairs ===========
__global__ __launch_bounds__(256, 2) void k_off2()
{
    const int rg    = blockIdx.x;
    const int b     = blockIdx.y;
    const int chunk = blockIdx.z;
    const int tid = threadIdx.x;
    const int r   = tid >> 4;
    const int x0  = (tid & 15) * 4;
    const int y0  = rg * 16;
    const int cbase = chunk * 32;

    __shared__ __align__(16) float halo[2][20 * 72];
    __shared__ __align__(16) float wt[32 * 9 * 18];

    for (int i = tid; i < 288 * 18; i += 256)
        wt[i] = g_wofft[(size_t)cbase * 9 * 18 + i];

    const float* plbase = g_out1 + ((size_t)b * PLANES + cbase) * HW;

    unsigned long long acc2[9][4];
#pragma unroll
    for (int op = 0; op < 9; ++op)
#pragma unroll
        for (int j = 0; j < 4; ++j) acc2[op][j] = 0ull;

    for (int i = tid; i < 1440; i += 256) {
        int ry = i / 72, rx = i % 72;
        int gy = y0 - 2 + ry, gx = rx - 2;
        halo[0][i] = ((unsigned)gy < 64u && (unsigned)gx < 64u)
                     ? plbase[gy * 64 + gx] : 0.f;
    }
    __syncthreads();

    for (int cl = 0; cl < 32; ++cl) {
        int buf = cl & 1;
        float fv[6];
        if (cl < 31) {
            const float* pl = plbase + (size_t)(cl + 1) * HW;
#pragma unroll
            for (int i = 0; i < 6; ++i) {
                int idx = tid + i * 256;
                float v = 0.f;
                if (idx < 1440) {
                    int ry = idx / 72, rx = idx % 72;
                    int gy = y0 - 2 + ry, gx = rx - 2;
                    if ((unsigned)gy < 64u && (unsigned)gx < 64u) v = pl[gy * 64 + gx];
                }
                fv[i] = v;
            }
        }
        const float* hb = &halo[buf][0];
#pragma unroll
        for (int t = 0; t < 9; ++t) {
            int dy = (t / 3) * 2, dx = (t % 3) * 2;
            const float* hp = hb + (r + dy) * 72 + x0 + dx;
            float2 sA = *(const float2*)hp;
            float2 sB = *(const float2*)(hp + 2);
            unsigned long long d0 = dup2(sA.x), d1 = dup2(sA.y);
            unsigned long long d2 = dup2(sB.x), d3 = dup2(sB.y);
            const float* wrow = &wt[(cl * 9 + t) * 18];
#pragma unroll
            for (int op = 0; op < 9; ++op) {
                float2 wp = *(const float2*)&wrow[op * 2];
                unsigned long long wv = pk2(wp.x, wp.y);
                fma2(acc2[op][0], wv, d0);
                fma2(acc2[op][1], wv, d1);
                fma2(acc2[op][2], wv, d2);
                fma2(acc2[op][3], wv, d3);
            }
        }
        if (cl < 31) {
#pragma unroll
            for (int i = 0; i < 6; ++i) {
                int idx = tid + i * 256;
                if (idx < 1440) halo[buf ^ 1][idx] = fv[i];
            }
        }
        __syncthreads();
    }

    const int px = (y0 + r) * 64 + x0;
    float* ob = g_off + (size_t)b * 18 * HW + px;
#pragma unroll
    for (int op = 0; op < 9; ++op)
#pragma unroll
        for (int j = 0; j < 4; ++j) {
            float lo, hi;
            unpk2(acc2[op][j], lo, hi);
            atomicAdd(ob + (size_t)(2 * op)     * HW + j, lo);
            atomicAdd(ob + (size_t)(2 * op + 1) * HW + j, hi);
        }
}

// ================ deform conv via mma.sync bf16x3 (BK=16, N=128, tap-major K) ======
// CTA: M=256 x N=128, K=2304 tap-major in 144 chunks of 16 (16 chunks per tap).
// buildB: thread owns one pixel + 4 channels; bilinear metadata cached in
// registers for the 16 consecutive chunks of each tap.
__global__ __launch_bounds__(512, 1) void k_deform_mma(
    const float* __restrict__ bc2,
    const float* __restrict__ ga, const float* __restrict__ be,
    const float* __restrict__ mu, const float* __restrict__ va)
{
    extern __shared__ __align__(16) char sm[];
    const int tid = threadIdx.x;
    const int lane = tid & 31, wid = tid >> 5;
    const int mbase = (wid >> 2) * 64, nbase = (wid & 3) * 32;
    const int b = blockIdx.y, n0 = blockIdx.x * 128;
    const float* out1b = g_out1 + (size_t)b * PLANES * HW;
    const float* offb  = g_off  + (size_t)b * 18 * HW;
    __nv_bfloat16* Oh = g_out2h + (size_t)b * PLANES * HW;
    __nv_bfloat16* Ol = g_out2l + (size_t)b * PLANES * HW;
    const uint32_t base = (uint32_t)__cvta_generic_to_shared(sm);

    if (tid < 256) {
        float s = ga[tid] * rsqrtf(va[tid] + EPS);
        float t = be[tid] - mu[tid] * s + bc2[tid] * s;
        ((float*)(sm + DF_S))[tid] = s;
        ((float*)(sm + DF_T))[tid] = t;
    }

    ushort4* MIDX = (ushort4*)(sm + DF_MIDX);
    float4*  MW   = (float4*) (sm + DF_MW);
    for (int idx = tid; idx < 9 * 128; idx += 512) {
        int k = idx >> 7, j = idx & 127;
        int p = n0 + j;
        int h = p >> 6, w = p & 63;
        float oy = offb[(size_t)(2 * k)     * HW + p];
        float ox = offb[(size_t)(2 * k + 1) * HW + p];
        float py = (float)(h + (k / 3) * 2 - 2) + oy;
        float px = (float)(w + (k % 3) * 2 - 2) + ox;
        float fy = floorf(py), fx = floorf(px);
        int y0 = (int)fy, x0 = (int)fx;
        float wy = py - fy, wx = px - fx;
        bool y0v = (unsigned)y0 < 64u, y1v = (unsigned)(y0 + 1) < 64u;
        bool x0v = (unsigned)x0 < 64u, x1v = (unsigned)(x0 + 1) < 64u;
        float w00 = (1.f - wy) * (1.f - wx) * (float)(y0v && x0v);
        float w01 = (1.f - wy) * wx         * (float)(y0v && x1v);
        float w10 = wy * (1.f - wx)         * (float)(y1v && x0v);
        float w11 = wy * wx                 * (float)(y1v && x1v);
        int y0c = min(max(y0, 0), 63),  y1c = min(max(y0 + 1, 0), 63);
        int x0c = min(max(x0, 0), 63),  x1c = min(max(x0 + 1, 0), 63);
        MIDX[idx] = make_ushort4((unsigned short)(y0c * 64 + x0c),
                                 (unsigned short)(y0c * 64 + x1c),
                                 (unsigned short)(y1c * 64 + x0c),
                                 (unsigned short)(y1c * 64 + x1c));
        MW[idx]   = make_float4(w00, w01, w10, w11);
    }
    __syncthreads();

    float acc[4][4][4];
#pragma unroll
    for (int i = 0; i < 4; ++i)
#pragma unroll
        for (int j = 0; j < 4; ++j)
#pragma unroll
            for (int q = 0; q < 4; ++q) acc[i][j][q] = 0.f;

    const int arow = tid >> 1;          // 0..255
    const int apart = (tid & 1) * 8;

#define DF_CPA(kc, buf)                                                          \
    do {                                                                         \
        cp16(sm + DF_AH + (((buf) * 256 + arow) * 24 + apart) * 2,               \
             g_w2h + (size_t)arow * 2304 + (kc) * 16 + apart);                   \
        cp16(sm + DF_AL + (((buf) * 256 + arow) * 24 + apart) * 2,               \
             g_w2l + (size_t)arow * 2304 + (kc) * 16 + apart);                   \
        cp_commit();                                                             \
    } while (0)

    // buildB thread mapping: pixel = tid & 127, channel group = tid >> 7 (4 ch)
    const int gpix = tid & 127;
    const int gcg  = (tid >> 7) * 4;    // 0,4,8,12
    ushort4 rid = make_ushort4(0, 0, 0, 0);
    float4  rw  = make_float4(0.f, 0.f, 0.f, 0.f);

    auto buildB = [&](int kc, int buf) {
        if ((kc & 15) == 0) {           // new tap: reload metadata (t = kc>>4)
            int mi = (kc >> 4) * 128 + gpix;
            rid = MIDX[mi];
            rw  = MW[mi];
        }
        const int c0 = ((kc & 15) << 4) + gcg;   // global channel of first elem
#pragma unroll
        for (int j = 0; j < 4; ++j) {
            const float* pl = out1b + (size_t)(c0 + j) * HW;
            float v = pl[rid.x] * rw.x;
            v = fmaf(pl[rid.y], rw.y, v);
            v = fmaf(pl[rid.z], rw.z, v);
            v = fmaf(pl[rid.w], rw.w, v);
            __nv_bfloat16 h, l;
            split_bf16(v, h, l);
            int off = ((buf * 16 + gcg + j) * 136 + gpix) * 2;
            *(__nv_bfloat16*)(sm + DF_BH + off) = h;
            *(__nv_bfloat16*)(sm + DF_BL + off) = l;
        }
    };

    DF_CPA(0, 0);
    buildB(0, 0);
    cp_wait0();
    __syncthreads();

    const int NC = 144;
    for (int kc = 0; kc < NC; ++kc) {
        const int buf = kc & 1;
        if (kc + 1 < NC) DF_CPA(kc + 1, buf ^ 1);
        {
            uint32_t ah[4][4], al[4][4];
#pragma unroll
            for (int mf = 0; mf < 4; ++mf) {
                uint32_t ro = ((buf * 256 + mbase + mf * 16 + (lane & 15)) * 24
                               + (lane >> 4) * 8) * 2;
                ldmA(ah[mf], base + DF_AH + ro);
                ldmA(al[mf], base + DF_AL + ro);
            }
#pragma unroll
            for (int np = 0; np < 2; ++np) {
                uint32_t ro = ((buf * 16 + (lane & 15)) * 136
                               + nbase + np * 16 + (lane >> 4) * 8) * 2;
                uint32_t bh[4], bl[4];
                ldmB4(bh, base + DF_BH + ro);
                ldmB4(bl, base + DF_BL + ro);
#pragma unroll
                for (int mf = 0; mf < 4; ++mf) {
                    mma16816(acc[mf][2 * np],     ah[mf], bh);
                    mma16816(acc[mf][2 * np],     ah[mf], bl);
                    mma16816(acc[mf][2 * np],     al[mf], bh);
                    mma16816(acc[mf][2 * np + 1], ah[mf], bh + 2);
                    mma16816(acc[mf][2 * np + 1], ah[mf], bl + 2);
                    mma16816(acc[mf][2 * np + 1], al[mf], bh + 2);
                }
            }
        }
        if (kc + 1 < NC) buildB(kc + 1, buf ^ 1);
        cp_wait0();
        __syncthreads();
    }

    const int quad = lane >> 2, tq = lane & 3;
    const float* sS = (const float*)(sm + DF_S);
    const float* sT = (const float*)(sm + DF_T);
#pragma unroll
    for (int mf = 0; mf < 4; ++mf) {
        int r0 = mbase + mf * 16 + quad;
        float s0 = sS[r0], t0 = sT[r0], s1 = sS[r0 + 8], t1 = sT[r0 + 8];
#pragma unroll
        for (int nf = 0; nf < 4; ++nf) {
            int c = nbase + nf * 8 + tq * 2;
            float y00 = fmaxf(acc[mf][nf][0] * s0 + t0, 0.f);
            float y01 = fmaxf(acc[mf][nf][1] * s0 + t0, 0.f);
            float y10 = fmaxf(acc[mf][nf][2] * s1 + t1, 0.f);
            float y11 = fmaxf(acc[mf][nf][3] * s1 + t1, 0.f);
            __nv_bfloat16 h0, l0, h1, l1, h2, l2, h3, l3;
            split_bf16(y00, h0, l0); split_bf16(y01, h1, l1);
            split_bf16(y10, h2, l2); split_bf16(y11, h3, l3);
            __nv_bfloat162 hA(h0, h1), lA(l0, l1), hB(h2, h3), lB(l2, l3);
            size_t gi0 = (size_t)r0 * HW + n0 + c;
            size_t gi1 = gi0 + (size_t)8 * HW;
            *(uint32_t*)&Oh[gi0] = *(uint32_t*)&hA;
            *(uint32_t*)&Ol[gi0] = *(uint32_t*)&lA;
            *(uint32_t*)&Oh[gi1] = *(uint32_t*)&hB;
            *(uint32_t*)&Ol[gi1] = *(uint32_t*)&lB;
        }
    }
}

// ---------------- launch ----------------
extern "C" void kernel_launch(void* const* d_in, const int* in_sizes, int n_in,
                              void* d_out, int out_size) {
    const float* x      = (const float*)d_in[0];
    const float* w1     = (const float*)d_in[1];
    const float* gamma1 = (const float*)d_in[2];
    const float* beta1  = (const float*)d_in[3];
    const float* mean1  = (const float*)d_in[4];
    const float* var1   = (const float*)d_in[5];
    const float* woff   = (const float*)d_in[6];
    const float* boff   = (const float*)d_in[7];
    const float* w2     = (const float*)d_in[8];
    const float* bconv2 = (const float*)d_in[9];
    const float* gamma2 = (const float*)d_in[10];
    const float* beta2  = (const float*)d_in[11];
    const float* mean2  = (const float*)d_in[12];
    const float* var2   = (const float*)d_in[13];
    const float* w3     = (const float*)d_in[14];
    const float* gamma3 = (const float*)d_in[15];
    const float* beta3  = (const float*)d_in[16];
    const float* mean3  = (const float*)d_in[17];
    const float* var3   = (const float*)d_in[18];

    cudaFuncSetAttribute(k_conv1_mma, cudaFuncAttributeMaxDynamicSharedMemorySize, MM_SMEM);
    cudaFuncSetAttribute(k_conv3_mma, cudaFuncAttributeMaxDynamicSharedMemorySize, MM_SMEM);
    cudaFuncSetAttribute(k_deform_mma, cudaFuncAttributeMaxDynamicSharedMemorySize, DF_SMEM);

    k_prep<<<5666, 256>>>(w1, w2, w3, woff, boff);
    k_conv1_mma<<<dim3(16, 2, BATCH), 512, MM_SMEM>>>(x, gamma1, beta1, mean1, var1);
    k_off2<<<dim3(4, BATCH, 8), 256>>>();
    k_deform_mma<<<dim3(32, BATCH), 512, DF_SMEM>>>(bconv2, gamma2, beta2, mean2, var2);
    k_conv3_mma<<<dim3(16, 8, BATCH), 512, MM_SMEM>>>(x, gamma3, beta3, mean3, var3,
                                                      (float*)d_out);
}

// round 17
// speedup vs baseline: 1.2883x; 1.0299x over previous
#include <cuda_runtime.h>
#include <cuda_bf16.h>
#include <cstdint>

#define EPS    1e-5f
#define CIN    1024
#define PLANES 256
#define HW     4096
#define BATCH  4

// ---------------- scratch (device globals; no allocation) ----------------
__device__ float g_out1[BATCH * PLANES * HW];          // conv1 output fp32 [b][c][p]
__device__ __nv_bfloat16 g_out2h[BATCH * PLANES * HW]; // deform output bf16 hi
__device__ __nv_bfloat16 g_out2l[BATCH * PLANES * HW]; // deform output bf16 lo
__device__ float g_off [BATCH * 18 * HW];
__device__ float g_wofft[2304 * 18];                   // [(c*9+t)][oc]
__device__ __nv_bfloat16 g_w1h[PLANES * CIN];
__device__ __nv_bfloat16 g_w1l[PLANES * CIN];
__device__ __nv_bfloat16 g_w2h[PLANES * 2304];         // tap-major: [o][t*256+c]
__device__ __nv_bfloat16 g_w2l[PLANES * 2304];
__device__ __nv_bfloat16 g_w3h[CIN * PLANES];
__device__ __nv_bfloat16 g_w3l[CIN * PLANES];

// ---------------- f32x2 packed-FMA helpers (off2) ----------------
__device__ __forceinline__ unsigned long long pk2(float lo, float hi) {
    unsigned long long r;
    asm("mov.b64 %0, {%1, %2};" : "=l"(r) : "f"(lo), "f"(hi));
    return r;
}
__device__ __forceinline__ unsigned long long dup2(float v) { return pk2(v, v); }
__device__ __forceinline__ void fma2(unsigned long long& d, unsigned long long a,
                                     unsigned long long b) {
    asm("fma.rn.f32x2 %0, %1, %2, %0;" : "+l"(d) : "l"(a), "l"(b));
}
__device__ __forceinline__ void unpk2(unsigned long long v, float& lo, float& hi) {
    asm("mov.b64 {%0, %1}, %2;" : "=f"(lo), "=f"(hi) : "l"(v));
}

// ---------------- cp.async helpers ----------------
__device__ __forceinline__ void cp16(void* dst, const void* src) {
    unsigned d = (unsigned)__cvta_generic_to_shared(dst);
    asm volatile("cp.async.ca.shared.global [%0], [%1], 16;" :: "r"(d), "l"(src));
}
__device__ __forceinline__ void cp_commit() { asm volatile("cp.async.commit_group;" ::: "memory"); }
__device__ __forceinline__ void cp_wait0()  { asm volatile("cp.async.wait_group 0;" ::: "memory"); }

// ---------------- mma.sync helpers ----------------
__device__ __forceinline__ void ldmA(uint32_t* r, uint32_t addr) {
    asm volatile("ldmatrix.sync.aligned.m8n8.x4.shared.b16 {%0,%1,%2,%3}, [%4];"
        : "=r"(r[0]), "=r"(r[1]), "=r"(r[2]), "=r"(r[3]) : "r"(addr));
}
__device__ __forceinline__ void ldmB4(uint32_t* r, uint32_t addr) {
    asm volatile("ldmatrix.sync.aligned.m8n8.x4.trans.shared.b16 {%0,%1,%2,%3}, [%4];"
        : "=r"(r[0]), "=r"(r[1]), "=r"(r[2]), "=r"(r[3]) : "r"(addr));
}
__device__ __forceinline__ void mma16816(float* c, const uint32_t* a, const uint32_t* b) {
    asm volatile("mma.sync.aligned.m16n8k16.row.col.f32.bf16.bf16.f32 "
        "{%0,%1,%2,%3}, {%4,%5,%6,%7}, {%8,%9}, {%0,%1,%2,%3};"
        : "+f"(c[0]), "+f"(c[1]), "+f"(c[2]), "+f"(c[3])
        : "r"(a[0]), "r"(a[1]), "r"(a[2]), "r"(a[3]), "r"(b[0]), "r"(b[1]));
}
__device__ __forceinline__ void split_bf16(float v, __nv_bfloat16& h, __nv_bfloat16& l) {
    h = __float2bfloat16(v);
    l = __float2bfloat16(v - __bfloat162float(h));
}

// smem layout for conv1/conv3 mma kernels (BK=16)
#define MM_AH 0
#define MM_AL 12288
#define MM_BH 24576
#define MM_BL 41472
#define MM_S  58368
#define MM_T  58880
#define MM_SMEM 59392

// smem layout for deform mma kernel (BK=16, N=128, 4 buffers)
#define DF_AH   0                      // [4][256][24] bf16 = 49152
#define DF_AL   49152                  // 49152
#define DF_BH   98304                  // [4][16][136] bf16 = 17408
#define DF_BL   115712                 // 17408
#define DF_MIDX 133120                 // ushort4[1152] = 9216
#define DF_MW   142336                 // float4[1152]  = 18432
#define DF_S    160768                 // float[256]
#define DF_T    161792                 // float[256]
#define DF_SMEM 162816

// ---------------- merged prep kernel ----------------
// grid ranges: [0,1024) w1-split | [1024,3328) w2-split (tap-major dst) |
//              [3328,4352) w3-split | [4352,4514) wofft | [4514,5666) offinit
__global__ void k_prep(const float* __restrict__ w1, const float* __restrict__ w2,
                       const float* __restrict__ w3, const float* __restrict__ woff,
                       const float* __restrict__ boff) {
    const int bid = blockIdx.x, tid = threadIdx.x;
    if (bid < 1024) {
        int i = bid * 256 + tid;
        float v = w1[i];
        __nv_bfloat16 hh = __float2bfloat16(v);
        g_w1h[i] = hh;
        g_w1l[i] = __float2bfloat16(v - __bfloat162float(hh));
    } else if (bid < 3328) {
        int i = (bid - 1024) * 256 + tid;        // dst index: o*2304 + t*256 + c
        int o = i / 2304, kk = i - o * 2304;
        int t = kk >> 8, c = kk & 255;
        float v = w2[(size_t)o * 2304 + c * 9 + t];
        __nv_bfloat16 hh = __float2bfloat16(v);
        g_w2h[i] = hh;
        g_w2l[i] = __float2bfloat16(v - __bfloat162float(hh));
    } else if (bid < 4352) {
        int i = (bid - 3328) * 256 + tid;
        float v = w3[i];
        __nv_bfloat16 hh = __float2bfloat16(v);
        g_w3h[i] = hh;
        g_w3l[i] = __float2bfloat16(v - __bfloat162float(hh));
    } else if (bid < 4514) {
        int i = (bid - 4352) * 256 + tid;
        if (i < 2304 * 18) {
            int ck = i / 18, oc = i - ck * 18;
            g_wofft[i] = woff[(size_t)oc * 2304 + ck];
        }
    } else {
        int i = (bid - 4514) * 256 + tid;
        if (i < BATCH * 18 * HW) {
            int oc = (i >> 12) % 18;
            g_off[i] = boff[oc];
        }
    }
}

// ================ conv1 (1x1)+BN1+ReLU via mma.sync bf16x3 (BK=16) ================
__global__ __launch_bounds__(512, 1) void k_conv1_mma(
    const float* __restrict__ X,
    const float* __restrict__ ga, const float* __restrict__ be,
    const float* __restrict__ mu, const float* __restrict__ va)
{
    extern __shared__ __align__(16) char sm[];
    const int tid = threadIdx.x;
    const int lane = tid & 31, wid = tid >> 5;
    const int mbase = (wid >> 3) * 64, nbase = (wid & 7) * 32;
    const int b = blockIdx.z, m0 = blockIdx.y * 128, n0 = blockIdx.x * 256;
    const float* Xb = X + (size_t)b * CIN * HW + n0;
    float* O = g_out1 + (size_t)b * PLANES * HW + n0;
    const uint32_t base = (uint32_t)__cvta_generic_to_shared(sm);

    if (tid < 128) {
        int o = m0 + tid;
        float s = ga[o] * rsqrtf(va[o] + EPS);
        ((float*)(sm + MM_S))[tid] = s;
        ((float*)(sm + MM_T))[tid] = be[o] - mu[o] * s;
    }

    float acc[4][4][4];
#pragma unroll
    for (int i = 0; i < 4; ++i)
#pragma unroll
        for (int j = 0; j < 4; ++j)
#pragma unroll
            for (int q = 0; q < 4; ++q) acc[i][j][q] = 0.f;

    const int half = tid & 1;
    const int arow = (tid >> 1) & 127;
    const int asel = tid >> 8;
    const __nv_bfloat16* aw = asel ? g_w1l : g_w1h;
    const int adst = (asel ? MM_AL : MM_AH);

    float4 pv0, pv1;
    const int i0k = tid >> 6,        i0c = (tid & 63) * 4;
    const int i1k = (tid + 512) >> 6, i1c = ((tid + 512) & 63) * 4;

#define C1_CPA(kc, buf)                                                          \
    do {                                                                         \
        cp16(sm + adst + (((buf) * 128 + arow) * 24 + half * 8) * 2,             \
             aw + (size_t)(m0 + arow) * CIN + (kc) * 16 + half * 8);             \
        cp_commit();                                                             \
    } while (0)
#define C1_LDB(kc)                                                               \
    do {                                                                         \
        pv0 = *(const float4*)&Xb[(size_t)((kc) * 16 + i0k) * HW + i0c];         \
        pv1 = *(const float4*)&Xb[(size_t)((kc) * 16 + i1k) * HW + i1c];         \
    } while (0)
#define C1_STB1(v, k, c4, buf)                                                   \
    do {                                                                         \
        __nv_bfloat16 h0, l0, h1, l1, h2, l2, h3, l3;                            \
        split_bf16((v).x, h0, l0); split_bf16((v).y, h1, l1);                    \
        split_bf16((v).z, h2, l2); split_bf16((v).w, h3, l3);                    \
        __nv_bfloat162 hA(h0, h1), hB(h2, h3), lA(l0, l1), lB(l2, l3);           \
        int off = (((buf) * 16 + (k)) * 264 + (c4)) * 2;                         \
        *(uint2*)(sm + MM_BH + off) = make_uint2(*(uint32_t*)&hA, *(uint32_t*)&hB); \
        *(uint2*)(sm + MM_BL + off) = make_uint2(*(uint32_t*)&lA, *(uint32_t*)&lB); \
    } while (0)

    C1_LDB(0);
    C1_CPA(0, 0);
    C1_STB1(pv0, i0k, i0c, 0);
    C1_STB1(pv1, i1k, i1c, 0);
    cp_wait0();
    __syncthreads();

    const int NC = CIN / 16;
    for (int kc = 0; kc < NC; ++kc) {
        const int buf = kc & 1;
        if (kc + 1 < NC) { C1_LDB(kc + 1); C1_CPA(kc + 1, buf ^ 1); }
        {
            uint32_t ah[4][4], al[4][4];
#pragma unroll
            for (int mf = 0; mf < 4; ++mf) {
                uint32_t ro = ((buf * 128 + mbase + mf * 16 + (lane & 15)) * 24
                               + (lane >> 4) * 8) * 2;
                ldmA(ah[mf], base + MM_AH + ro);
                ldmA(al[mf], base + MM_AL + ro);
            }
#pragma unroll
            for (int np = 0; np < 2; ++np) {
                uint32_t ro = ((buf * 16 + (lane & 15)) * 264
                               + nbase + np * 16 + (lane >> 4) * 8) * 2;
                uint32_t bh[4], bl[4];
                ldmB4(bh, base + MM_BH + ro);
                ldmB4(bl, base + MM_BL + ro);
#pragma unroll
                for (int mf = 0; mf < 4; ++mf) {
                    mma16816(acc[mf][2 * np],     ah[mf], bh);
                    mma16816(acc[mf][2 * np],     ah[mf], bl);
                    mma16816(acc[mf][2 * np],     al[mf], bh);
                    mma16816(acc[mf][2 * np + 1], ah[mf], bh + 2);
                    mma16816(acc[mf][2 * np + 1], ah[mf], bl + 2);
                    mma16816(acc[mf][2 * np + 1], al[mf], bh + 2);
                }
            }
        }
        if (kc + 1 < NC) { C1_STB1(pv0, i0k, i0c, buf ^ 1); C1_STB1(pv1, i1k, i1c, buf ^ 1); }
        cp_wait0();
        __syncthreads();
    }

    const int quad = lane >> 2, tq = lane & 3;
    const float* sS = (const float*)(sm + MM_S);
    const float* sT = (const float*)(sm + MM_T);
#pragma unroll
    for (int mf = 0; mf < 4; ++mf) {
        int r0 = mbase + mf * 16 + quad;
        float s0 = sS[r0], t0 = sT[r0], s1 = sS[r0 + 8], t1 = sT[r0 + 8];
#pragma unroll
        for (int nf = 0; nf < 4; ++nf) {
            int c = nbase + nf * 8 + tq * 2;
            float2 v0, v1;
            v0.x = fmaxf(acc[mf][nf][0] * s0 + t0, 0.f);
            v0.y = fmaxf(acc[mf][nf][1] * s0 + t0, 0.f);
            v1.x = fmaxf(acc[mf][nf][2] * s1 + t1, 0.f);
            v1.y = fmaxf(acc[mf][nf][3] * s1 + t1, 0.f);
            *(float2*)&O[(size_t)(m0 + r0) * HW + c]     = v0;
            *(float2*)&O[(size_t)(m0 + r0 + 8) * HW + c] = v1;
        }
    }
}

// ================ conv3 (1x1)+BN3+residual+ReLU via mma.sync bf16x3 (BK=16) =========
__global__ __launch_bounds__(512, 1) void k_conv3_mma(
    const float* __restrict__ X,
    const float* __restrict__ ga, const float* __restrict__ be,
    const float* __restrict__ mu, const float* __restrict__ va,
    float* __restrict__ OUT)
{
    extern __shared__ __align__(16) char sm[];
    const int tid = threadIdx.x;
    const int lane = tid & 31, wid = tid >> 5;
    const int mbase = (wid >> 3) * 64, nbase = (wid & 7) * 32;
    const int b = blockIdx.z, m0 = blockIdx.y * 128, n0 = blockIdx.x * 256;
    const uint32_t base = (uint32_t)__cvta_generic_to_shared(sm);

    if (tid < 128) {
        int o = m0 + tid;
        float s = ga[o] * rsqrtf(va[o] + EPS);
        ((float*)(sm + MM_S))[tid] = s;
        ((float*)(sm + MM_T))[tid] = be[o] - mu[o] * s;
    }

    float acc[4][4][4];
#pragma unroll
    for (int i = 0; i < 4; ++i)
#pragma unroll
        for (int j = 0; j < 4; ++j)
#pragma unroll
            for (int q = 0; q < 4; ++q) acc[i][j][q] = 0.f;

    const int half = tid & 1;
    const int arow = (tid >> 1) & 127;
    const int asel = tid >> 8;
    const __nv_bfloat16* aw = asel ? g_w3l : g_w3h;
    const int adst = (asel ? MM_AL : MM_AH);
    const int j0 = tid, j1 = tid + 512;
    const int b0sel = j0 >> 9, b0k = (j0 & 511) >> 5, b0q = (j0 & 31) * 8;
    const int b1sel = j1 >> 9, b1k = (j1 & 511) >> 5, b1q = (j1 & 31) * 8;
    const __nv_bfloat16* bsrc0 = (b0sel ? g_out2l : g_out2h) + (size_t)b * PLANES * HW + n0;
    const __nv_bfloat16* bsrc1 = (b1sel ? g_out2l : g_out2h) + (size_t)b * PLANES * HW + n0;
    const int bdst0 = b0sel ? MM_BL : MM_BH;
    const int bdst1 = b1sel ? MM_BL : MM_BH;

#define C3_CP(kc, buf)                                                            \
    do {                                                                          \
        cp16(sm + adst + (((buf) * 128 + arow) * 24 + half * 8) * 2,              \
             aw + (size_t)(m0 + arow) * PLANES + (kc) * 16 + half * 8);           \
        cp16(sm + bdst0 + (((buf) * 16 + b0k) * 264 + b0q) * 2,                   \
             bsrc0 + (size_t)((kc) * 16 + b0k) * HW + b0q);                       \
        cp16(sm + bdst1 + (((buf) * 16 + b1k) * 264 + b1q) * 2,                   \
             bsrc1 + (size_t)((kc) * 16 + b1k) * HW + b1q);                       \
        cp_commit();                                                              \
    } while (0)

    C3_CP(0, 0);
    cp_wait0();
    __syncthreads();

    const int NC = PLANES / 16;
    for (int kc = 0; kc < NC; ++kc) {
        const int buf = kc & 1;
        if (kc + 1 < NC) C3_CP(kc + 1, buf ^ 1);
        {
            uint32_t ah[4][4], al[4][4];
#pragma unroll
            for (int mf = 0; mf < 4; ++mf) {
                uint32_t ro = ((buf * 128 + mbase + mf * 16 + (lane & 15)) * 24
                               + (lane >> 4) * 8) * 2;
                ldmA(ah[mf], base + MM_AH + ro);
                ldmA(al[mf], base + MM_AL + ro);
            }
#pragma unroll
            for (int np = 0; np < 2; ++np) {
                uint32_t ro = ((buf * 16 + (lane & 15)) * 264
                               + nbase + np * 16 + (lane >> 4) * 8) * 2;
                uint32_t bh[4], bl[4];
                ldmB4(bh, base + MM_BH + ro);
                ldmB4(bl, base + MM_BL + ro);
#pragma unroll
                for (int mf = 0; mf < 4; ++mf) {
                    mma16816(acc[mf][2 * np],     ah[mf], bh);
                    mma16816(acc[mf][2 * np],     ah[mf], bl);
                    mma16816(acc[mf][2 * np],     al[mf], bh);
                    mma16816(acc[mf][2 * np + 1], ah[mf], bh + 2);
                    mma16816(acc[mf][2 * np + 1], ah[mf], bl + 2);
                    mma16816(acc[mf][2 * np + 1], al[mf], bh + 2);
                }
            }
        }
        cp_wait0();
        __syncthreads();
    }

    const int quad = lane >> 2, tq = lane & 3;
    const float* sS = (const float*)(sm + MM_S);
    const float* sT = (const float*)(sm + MM_T);
#pragma unroll
    for (int mf = 0; mf < 4; ++mf) {
        int r0 = mbase + mf * 16 + quad;
        float s0 = sS[r0], t0 = sT[r0], s1 = sS[r0 + 8], t1 = sT[r0 + 8];
#pragma unroll
        for (int nf = 0; nf < 4; ++nf) {
            int c = nbase + nf * 8 + tq * 2;
            size_t gi0 = ((size_t)b * CIN + m0 + r0) * HW + n0 + c;
            size_t gi1 = gi0 + (size_t)8 * HW;
            float2 x0 = *(const float2*)&X[gi0];
            float2 x1 = *(const float2*)&X[gi1];
            float2 v0, v1;
            v0.x = fmaxf(acc[mf][nf][0] * s0 + t0 + x0.x, 0.f);
            v0.y = fmaxf(acc[mf][nf][1] * s0 + t0 + x0.y, 0.f);
            v1.x = fmaxf(acc[mf][nf][2] * s1 + t1 + x1.x, 0.f);
            v1.y = fmaxf(acc[mf][nf][3] * s1 + t1 + x1.y, 0.f);
            *(float2*)&OUT[gi0] = v0;
            *(float2*)&OUT[gi1] = v1;
        }
    }
}

// ================ offset conv (3x3 dil=2, 18 oc) — f32x2 over oc pairs ===========
__global__ __launch_bounds__(256, 2) void k_off2()
{
    const int rg    = blockIdx.x;
    const int b     = blockIdx.y;
    const int chunk = blockIdx.z;
    const int tid = threadIdx.x;
    const int r   = tid >> 4;
    const int x0  = (tid & 15) * 4;
    const int y0  = rg * 16;
    const int cbase = chunk * 32;

    __shared__ __align__(16) float halo[2][20 * 72];
    __shared__ __align__(16) float wt[32 * 9 * 18];

    for (int i = tid; i < 288 * 18; i += 256)
        wt[i] = g_wofft[(size_t)cbase * 9 * 18 + i];

    const float* plbase = g_out1 + ((size_t)b * PLANES + cbase) * HW;

    unsigned long long acc2[9][4];
#pragma unroll
    for (int op = 0; op < 9; ++op)
#pragma unroll
        for (int j = 0; j < 4; ++j) acc2[op][j] = 0ull;

    for (int i = tid; i < 1440; i += 256) {
        int ry = i / 72, rx = i % 72;
        int gy = y0 - 2 + ry, gx = rx - 2;
        halo[0][i] = ((unsigned)gy < 64u && (unsigned)gx < 64u)
                     ? plbase[gy * 64 + gx] : 0.f;
    }
    __syncthreads();

    for (int cl = 0; cl < 32; ++cl) {
        int buf = cl & 1;
        float fv[6];
        if (cl < 31) {
            const float* pl = plbase + (size_t)(cl + 1) * HW;
#pragma unroll
            for (int i = 0; i < 6; ++i) {
                int idx = tid + i * 256;
                float v = 0.f;
                if (idx < 1440) {
                    int ry = idx / 72, rx = idx % 72;
                    int gy = y0 - 2 + ry, gx = rx - 2;
                    if ((unsigned)gy < 64u && (unsigned)gx < 64u) v = pl[gy * 64 + gx];
                }
                fv[i] = v;
            }
        }
        const float* hb = &halo[buf][0];
#pragma unroll
        for (int t = 0; t < 9; ++t) {
            int dy = (t / 3) * 2, dx = (t % 3) * 2;
            const float* hp = hb + (r + dy) * 72 + x0 + dx;
            float2 sA = *(const float2*)hp;
            float2 sB = *(const float2*)(hp + 2);
            unsigned long long d0 = dup2(sA.x), d1 = dup2(sA.y);
            unsigned long long d2 = dup2(sB.x), d3 = dup2(sB.y);
            const float* wrow = &wt[(cl * 9 + t) * 18];
#pragma unroll
            for (int op = 0; op < 9; ++op) {
                float2 wp = *(const float2*)&wrow[op * 2];
                unsigned long long wv = pk2(wp.x, wp.y);
                fma2(acc2[op][0], wv, d0);
                fma2(acc2[op][1], wv, d1);
                fma2(acc2[op][2], wv, d2);
                fma2(acc2[op][3], wv, d3);
            }
        }
        if (cl < 31) {
#pragma unroll
            for (int i = 0; i < 6; ++i) {
                int idx = tid + i * 256;
                if (idx < 1440) halo[buf ^ 1][idx] = fv[i];
            }
        }
        __syncthreads();
    }

    const int px = (y0 + r) * 64 + x0;
    float* ob = g_off + (size_t)b * 18 * HW + px;
#pragma unroll
    for (int op = 0; op < 9; ++op)
#pragma unroll
        for (int j = 0; j < 4; ++j) {
            float lo, hi;
            unpk2(acc2[op][j], lo, hi);
            atomicAdd(ob + (size_t)(2 * op)     * HW + j, lo);
            atomicAdd(ob + (size_t)(2 * op + 1) * HW + j, hi);
        }
}

// ================ deform conv via mma.sync bf16x3 (BK=16, N=128, tap-major K) ======
// 4 smem buffers, barrier every 2 chunks: round r computes chunks {2r,2r+1} from
// buffers {2r&3,(2r+1)&3} while filling {2r+2,2r+3} into the other buffer pair.
__global__ __launch_bounds__(512, 1) void k_deform_mma(
    const float* __restrict__ bc2,
    const float* __restrict__ ga, const float* __restrict__ be,
    const float* __restrict__ mu, const float* __restrict__ va)
{
    extern __shared__ __align__(16) char sm[];
    const int tid = threadIdx.x;
    const int lane = tid & 31, wid = tid >> 5;
    const int mbase = (wid >> 2) * 64, nbase = (wid & 3) * 32;
    const int b = blockIdx.y, n0 = blockIdx.x * 128;
    const float* out1b = g_out1 + (size_t)b * PLANES * HW;
    const float* offb  = g_off  + (size_t)b * 18 * HW;
    __nv_bfloat16* Oh = g_out2h + (size_t)b * PLANES * HW;
    __nv_bfloat16* Ol = g_out2l + (size_t)b * PLANES * HW;
    const uint32_t base = (uint32_t)__cvta_generic_to_shared(sm);

    if (tid < 256) {
        float s = ga[tid] * rsqrtf(va[tid] + EPS);
        float t = be[tid] - mu[tid] * s + bc2[tid] * s;
        ((float*)(sm + DF_S))[tid] = s;
        ((float*)(sm + DF_T))[tid] = t;
    }

    ushort4* MIDX = (ushort4*)(sm + DF_MIDX);
    float4*  MW   = (float4*) (sm + DF_MW);
    for (int idx = tid; idx < 9 * 128; idx += 512) {
        int k = idx >> 7, j = idx & 127;
        int p = n0 + j;
        int h = p >> 6, w = p & 63;
        float oy = offb[(size_t)(2 * k)     * HW + p];
        float ox = offb[(size_t)(2 * k + 1) * HW + p];
        float py = (float)(h + (k / 3) * 2 - 2) + oy;
        float px = (float)(w + (k % 3) * 2 - 2) + ox;
        float fy = floorf(py), fx = floorf(px);
        int y0 = (int)fy, x0 = (int)fx;
        float wy = py - fy, wx = px - fx;
        bool y0v = (unsigned)y0 < 64u, y1v = (unsigned)(y0 + 1) < 64u;
        bool x0v = (unsigned)x0 < 64u, x1v = (unsigned)(x0 + 1) < 64u;
        float w00 = (1.f - wy) * (1.f - wx) * (float)(y0v && x0v);
        float w01 = (1.f - wy) * wx         * (float)(y0v && x1v);
        float w10 = wy * (1.f - wx)         * (float)(y1v && x0v);
        float w11 = wy * wx                 * (float)(y1v && x1v);
        int y0c = min(max(y0, 0), 63),  y1c = min(max(y0 + 1, 0), 63);
        int x0c = min(max(x0, 0), 63),  x1c = min(max(x0 + 1, 0), 63);
        MIDX[idx] = make_ushort4((unsigned short)(y0c * 64 + x0c),
                                 (unsigned short)(y0c * 64 + x1c),
                                 (unsigned short)(y1c * 64 + x0c),
                                 (unsigned short)(y1c * 64 + x1c));
        MW[idx]   = make_float4(w00, w01, w10, w11);
    }
    __syncthreads();

    float acc[4][4][4];
#pragma unroll
    for (int i = 0; i < 4; ++i)
#pragma unroll
        for (int j = 0; j < 4; ++j)
#pragma unroll
            for (int q = 0; q < 4; ++q) acc[i][j][q] = 0.f;

    const int arow = tid >> 1;          // 0..255
    const int apart = (tid & 1) * 8;

    auto issueA = [&](int kc, int buf) {
        cp16(sm + DF_AH + ((buf * 256 + arow) * 24 + apart) * 2,
             g_w2h + (size_t)arow * 2304 + kc * 16 + apart);
        cp16(sm + DF_AL + ((buf * 256 + arow) * 24 + apart) * 2,
             g_w2l + (size_t)arow * 2304 + kc * 16 + apart);
    };

    // buildB thread mapping: pixel = tid & 127, channel group = tid >> 7 (4 ch)
    const int gpix = tid & 127;
    const int gcg  = (tid >> 7) * 4;    // 0,4,8,12
    ushort4 rid = make_ushort4(0, 0, 0, 0);
    float4  rw  = make_float4(0.f, 0.f, 0.f, 0.f);

    auto buildB = [&](int kc, int buf) {
        if ((kc & 15) == 0) {           // new tap: reload metadata (t = kc>>4)
            int mi = (kc >> 4) * 128 + gpix;
            rid = MIDX[mi];
            rw  = MW[mi];
        }
        const int c0 = ((kc & 15) << 4) + gcg;
#pragma unroll
        for (int j = 0; j < 4; ++j) {
            const float* pl = out1b + (size_t)(c0 + j) * HW;
            float v = pl[rid.x] * rw.x;
            v = fmaf(pl[rid.y], rw.y, v);
            v = fmaf(pl[rid.z], rw.z, v);
            v = fmaf(pl[rid.w], rw.w, v);
            __nv_bfloat16 h, l;
            split_bf16(v, h, l);
            int off = ((buf * 16 + gcg + j) * 136 + gpix) * 2;
            *(__nv_bfloat16*)(sm + DF_BH + off) = h;
            *(__nv_bfloat16*)(sm + DF_BL + off) = l;
        }
    };

    auto mmaChunk = [&](int buf) {
        uint32_t ah[4][4], al[4][4];
#pragma unroll
        for (int mf = 0; mf < 4; ++mf) {
            uint32_t ro = ((buf * 256 + mbase + mf * 16 + (lane & 15)) * 24
                           + (lane >> 4) * 8) * 2;
            ldmA(ah[mf], base + DF_AH + ro);
            ldmA(al[mf], base + DF_AL + ro);
        }
#pragma unroll
        for (int np = 0; np < 2; ++np) {
            uint32_t ro = ((buf * 16 + (lane & 15)) * 136
                           + nbase + np * 16 + (lane >> 4) * 8) * 2;
            uint32_t bh[4], bl[4];
            ldmB4(bh, base + DF_BH + ro);
            ldmB4(bl, base + DF_BL + ro);
#pragma unroll
            for (int mf = 0; mf < 4; ++mf) {
                mma16816(acc[mf][2 * np],     ah[mf], bh);
                mma16816(acc[mf][2 * np],     ah[mf], bl);
                mma16816(acc[mf][2 * np],     al[mf], bh);
                mma16816(acc[mf][2 * np + 1], ah[mf], bh + 2);
                mma16816(acc[mf][2 * np + 1], ah[mf], bl + 2);
                mma16816(acc[mf][2 * np + 1], al[mf], bh + 2);
            }
        }
    };

    // prologue: fill chunks 0 and 1
    issueA(0, 0);
    issueA(1, 1);
    cp_commit();
    buildB(0, 0);
    buildB(1, 1);
    cp_wait0();
    __syncthreads();

    const int NC = 144;
    for (int kc = 0; kc < NC; kc += 2) {
        if (kc + 2 < NC) {
            issueA(kc + 2, (kc + 2) & 3);
            issueA(kc + 3, (kc + 3) & 3);
            cp_commit();
        }
        mmaChunk(kc & 3);
        if (kc + 2 < NC) buildB(kc + 2, (kc + 2) & 3);
        mmaChunk((kc + 1) & 3);
        if (kc + 3 < NC) buildB(kc + 3, (kc + 3) & 3);
        cp_wait0();
        __syncthreads();
    }

    const int quad = lane >> 2, tq = lane & 3;
    const float* sS = (const float*)(sm + DF_S);
    const float* sT = (const float*)(sm + DF_T);
#pragma unroll
    for (int mf = 0; mf < 4; ++mf) {
        int r0 = mbase + mf * 16 + quad;
        float s0 = sS[r0], t0 = sT[r0], s1 = sS[r0 + 8], t1 = sT[r0 + 8];
#pragma unroll
        for (int nf = 0; nf < 4; ++nf) {
            int c = nbase + nf * 8 + tq * 2;
            float y00 = fmaxf(acc[mf][nf][0] * s0 + t0, 0.f);
            float y01 = fmaxf(acc[mf][nf][1] * s0 + t0, 0.f);
            float y10 = fmaxf(acc[mf][nf][2] * s1 + t1, 0.f);
            float y11 = fmaxf(acc[mf][nf][3] * s1 + t1, 0.f);
            __nv_bfloat16 h0, l0, h1, l1, h2, l2, h3, l3;
            split_bf16(y00, h0, l0); split_bf16(y01, h1, l1);
            split_bf16(y10, h2, l2); split_bf16(y11, h3, l3);
            __nv_bfloat162 hA(h0, h1), lA(l0, l1), hB(h2, h3), lB(l2, l3);
            size_t gi0 = (size_t)r0 * HW + n0 + c;
            size_t gi1 = gi0 + (size_t)8 * HW;
            *(uint32_t*)&Oh[gi0] = *(uint32_t*)&hA;
            *(uint32_t*)&Ol[gi0] = *(uint32_t*)&lA;
            *(uint32_t*)&Oh[gi1] = *(uint32_t*)&hB;
            *(uint32_t*)&Ol[gi1] = *(uint32_t*)&lB;
        }
    }
}

// ---------------- launch ----------------
extern "C" void kernel_launch(void* const* d_in, const int* in_sizes, int n_in,
                              void* d_out, int out_size) {
    const float* x      = (const float*)d_in[0];
    const float* w1     = (const float*)d_in[1];
    const float* gamma1 = (const float*)d_in[2];
    const float* beta1  = (const float*)d_in[3];
    const float* mean1  = (const float*)d_in[4];
    const float* var1   = (const float*)d_in[5];
    const float* woff   = (const float*)d_in[6];
    const float* boff   = (const float*)d_in[7];
    const float* w2     = (const float*)d_in[8];
    const float* bconv2 = (const float*)d_in[9];
    const float* gamma2 = (const float*)d_in[10];
    const float* beta2  = (const float*)d_in[11];
    const float* mean2  = (const float*)d_in[12];
    const float* var2   = (const float*)d_in[13];
    const float* w3     = (const float*)d_in[14];
    const float* gamma3 = (const float*)d_in[15];
    const float* beta3  = (const float*)d_in[16];
    const float* mean3  = (const float*)d_in[17];
    const float* var3   = (const float*)d_in[18];

    cudaFuncSetAttribute(k_conv1_mma, cudaFuncAttributeMaxDynamicSharedMemorySize, MM_SMEM);
    cudaFuncSetAttribute(k_conv3_mma, cudaFuncAttributeMaxDynamicSharedMemorySize, MM_SMEM);
    cudaFuncSetAttribute(k_deform_mma, cudaFuncAttributeMaxDynamicSharedMemorySize, DF_SMEM);

    k_prep<<<5666, 256>>>(w1, w2, w3, woff, boff);
    k_conv1_mma<<<dim3(16, 2, BATCH), 512, MM_SMEM>>>(x, gamma1, beta1, mean1, var1);
    k_off2<<<dim3(4, BATCH, 8), 256>>>();
    k_deform_mma<<<dim3(32, BATCH), 512, DF_SMEM>>>(bconv2, gamma2, beta2, mean2, var2);
    k_conv3_mma<<<dim3(16, 8, BATCH), 512, MM_SMEM>>>(x, gamma3, beta3, mean3, var3,
                                                      (float*)d_out);
}